// round 8
// baseline (speedup 1.0000x reference)
#include <cuda_runtime.h>
#include <cuda_bf16.h>
#include <math.h>
#include <stdint.h>

#define BATCH 8
#define NPTS  16384
#define M_KV  64
#define TOTM  (BATCH*NPTS)
#define P     16
#define PP    20
#define PITCH 257
typedef unsigned long long ull;

// ======== packed f32x2 helpers (scalar kernels) ========
__device__ __forceinline__ void fma2(ull& a, ull x, ull w) {
    asm("fma.rn.f32x2 %0, %1, %2, %0;" : "+l"(a) : "l"(x), "l"(w));
}
__device__ __forceinline__ float fold2(ull v) { float lo,hi; asm("mov.b64 {%0,%1}, %2;" : "=f"(lo),"=f"(hi) : "l"(v)); return lo+hi; }
__device__ __forceinline__ void unpack2(ull v, float& lo, float& hi) { asm("mov.b64 {%0,%1}, %2;" : "=f"(lo),"=f"(hi) : "l"(v)); }
__device__ __forceinline__ ull pack2(float lo, float hi) { ull r; asm("mov.b64 %0, {%1,%2};" : "=l"(r) : "f"(lo),"f"(hi)); return r; }

// ======== global scratch ========
#define SZ ((size_t)TOTM * 256)
__device__ __nv_bfloat16 g_X0h[SZ], g_X0l[SZ], g_X1h[SZ], g_X1l[SZ], g_Z2h[SZ], g_Z2l[SZ];
__device__ float g_Q[SZ];
__device__ __nv_bfloat16 g_Bh[12*65536], g_Bl[12*65536];
__device__ float g_Kt[BATCH*8*32*M_KV];
__device__ float g_Vt[BATCH*32*256*2];
__device__ __forceinline__ __nv_bfloat16* selH(int s){ return s==0?g_X0h:(s==1?g_X1h:g_Z2h); }
__device__ __forceinline__ __nv_bfloat16* selL(int s){ return s==0?g_X0l:(s==1?g_X1l:g_Z2l); }

// ======== prep kernels ========
__global__ void conv_w(const float* __restrict__ qp_W2, const float* __restrict__ in_W,
                       const float* __restrict__ out_W, const float* __restrict__ net2_W,
                       const float* __restrict__ net1_W) {
    int n = blockIdx.x, mat = blockIdx.y, k = threadIdx.x;
    const float* src;
    switch (mat) {
        case 0: src = qp_W2; break;
        case 1: src = in_W;  break;
        case 2: src = out_W; break;
        default: src = (mat < 8) ? net2_W + (mat-3)*65536 : net1_W + (mat-8)*65536;
    }
    float w = src[n*256 + k];
    __nv_bfloat16 h = __float2bfloat16_rn(w);
    g_Bh[mat*65536 + n*256 + k] = h;
    g_Bl[mat*65536 + n*256 + k] = __float2bfloat16_rn(w - __bfloat162float(h));
}

__global__ void kv_kernel(const float* __restrict__ z_multi,
                          const float* __restrict__ lnkv_g, const float* __restrict__ lnkv_b,
                          const float* __restrict__ in_W,  const float* __restrict__ in_b) {
    __shared__ float kvn[256], rs[8], rss[8];
    __shared__ float s_mu, s_rstd;
    int row = blockIdx.x, b = row >> 6, m = row & 63;
    int t = threadIdx.x, lane = t & 31, w = t >> 5;
    float v = z_multi[row*256 + t];
    float s = v, ss = v*v;
    #pragma unroll
    for (int o = 16; o; o >>= 1) {
        s  += __shfl_xor_sync(0xffffffffu, s,  o);
        ss += __shfl_xor_sync(0xffffffffu, ss, o);
    }
    if (lane == 0) { rs[w] = s; rss[w] = ss; }
    __syncthreads();
    if (t == 0) {
        float S=0.f, SS=0.f;
        for (int i = 0; i < 8; ++i) { S += rs[i]; SS += rss[i]; }
        float mu = S*(1.f/256.f);
        s_mu = mu; s_rstd = rsqrtf(SS*(1.f/256.f) - mu*mu + 1e-5f);
    }
    __syncthreads();
    kvn[t] = (v - s_mu) * s_rstd * lnkv_g[t] + lnkv_b[t];
    __syncthreads();
    float aK = in_b[256+t], aV = in_b[512+t];
    const float* wk = in_W + (size_t)(256+t)*256;
    const float* wv = in_W + (size_t)(512+t)*256;
    #pragma unroll 4
    for (int d = 0; d < 256; ++d) { float x = kvn[d]; aK += x*wk[d]; aV += x*wv[d]; }
    g_Kt[((b*8 + (t>>5))*32 + (t&31))*M_KV + m] = aK;
    g_Vt[((b*32 + (m>>1))*256 + t)*2 + (m&1)] = aV;
}

__global__ void gelu_kernel(const float* __restrict__ coords,
                            const float* __restrict__ qp_W1, const float* __restrict__ qp_b1) {
    int t = threadIdx.x;
    int pt0 = blockIdx.x * 8;
    float wx = qp_W1[2*t], wy = qp_W1[2*t+1], bb = qp_b1[t];
    #pragma unroll
    for (int p = 0; p < 8; ++p) {
        int pt = pt0 + p;
        float u = wx*coords[2*pt] + wy*coords[2*pt+1] + bb;
        float v = 0.5f*u*(1.f + erff(u*0.70710678118654752f));
        __nv_bfloat16 h = __float2bfloat16_rn(v);
        g_X0h[(size_t)pt*256 + t] = h;
        g_X0l[(size_t)pt*256 + t] = __float2bfloat16_rn(v - __bfloat162float(h));
    }
}

// ======== warp-MMA GEMM with fused epilogue ========
// C[64 x 256] = sum_s A_s[64 x 256] @ B_s^T,  bf16 split-3, fp32 accum.
// 8 warps: wm = w>>2 (M half), wn = w&3 (N quarter). Warp tile m32 x n64.
#define MODE_LN 0
#define MODE_Q 1
#define MODE_BIAS 2
#define MODE_BASIS 3
#define GEMM_SMEM (64*PITCH*4 + 256*4*2)

__global__ void __launch_bounds__(256)
gemm_mma(int mode, int L, int nsrc, int srcA1, int srcA2, int matB1, int matB2, int dst,
         const float* __restrict__ bias, float scale,
         const float* __restrict__ lng, const float* __restrict__ lnb,
         const float* __restrict__ gW, const float* __restrict__ gb,
         const float* __restrict__ gmu, const float* __restrict__ gga,
         const float* __restrict__ coords) {
    extern __shared__ float sC[];                // [64][PITCH]
    float* sRs  = sC + 64*PITCH;                 // [64][4]
    float* sRss = sRs + 256;                     // [64][4]

    int tid = threadIdx.x, lane = tid & 31, w = tid >> 5;
    int wn = w & 3, wm = w >> 2;
    int m_block = blockIdx.x * 64;
    int r4 = lane >> 2, kp = (lane & 3) * 2;

    float c[2][8][4];
    #pragma unroll
    for (int mt = 0; mt < 2; ++mt)
        #pragma unroll
        for (int nt = 0; nt < 8; ++nt)
            #pragma unroll
            for (int i = 0; i < 4; ++i) c[mt][nt][i] = 0.f;

    for (int s = 0; s < nsrc; ++s) {
        const __nv_bfloat16* AH = selH(s == 0 ? srcA1 : srcA2);
        const __nv_bfloat16* AL = selL(s == 0 ? srcA1 : srcA2);
        const __nv_bfloat16* BH = g_Bh + (size_t)((s == 0) ? matB1 : matB2) * 65536;
        const __nv_bfloat16* BL = g_Bl + (size_t)((s == 0) ? matB1 : matB2) * 65536;
        #pragma unroll
        for (int pass = 0; pass < 3; ++pass) {
            const __nv_bfloat16* A = (pass == 1) ? AL : AH;
            const __nv_bfloat16* W = (pass == 2) ? BL : BH;
            const __nv_bfloat16* Ab = A + (size_t)(m_block + wm*32 + r4)*256 + kp;
            const __nv_bfloat16* Wb = W + (size_t)(wn*64 + r4)*256 + kp;
            #pragma unroll 4
            for (int k0 = 0; k0 < 256; k0 += 16) {
                uint32_t b[8][2];
                #pragma unroll
                for (int nt = 0; nt < 8; ++nt) {
                    b[nt][0] = *(const uint32_t*)(Wb + nt*8*256 + k0);
                    b[nt][1] = *(const uint32_t*)(Wb + nt*8*256 + k0 + 8);
                }
                #pragma unroll
                for (int mt = 0; mt < 2; ++mt) {
                    uint32_t a0 = *(const uint32_t*)(Ab + mt*16*256 + k0);
                    uint32_t a1 = *(const uint32_t*)(Ab + (mt*16+8)*256 + k0);
                    uint32_t a2 = *(const uint32_t*)(Ab + mt*16*256 + k0 + 8);
                    uint32_t a3 = *(const uint32_t*)(Ab + (mt*16+8)*256 + k0 + 8);
                    #pragma unroll
                    for (int nt = 0; nt < 8; ++nt)
                        asm volatile("mma.sync.aligned.m16n8k16.row.col.f32.bf16.bf16.f32 "
                            "{%0,%1,%2,%3}, {%4,%5,%6,%7}, {%8,%9}, {%0,%1,%2,%3};"
                            : "+f"(c[mt][nt][0]), "+f"(c[mt][nt][1]),
                              "+f"(c[mt][nt][2]), "+f"(c[mt][nt][3])
                            : "r"(a0), "r"(a1), "r"(a2), "r"(a3),
                              "r"(b[nt][0]), "r"(b[nt][1]));
                }
            }
        }
    }

    // ---- stage fragments to smem ----
    #pragma unroll
    for (int mt = 0; mt < 2; ++mt) {
        int rl = wm*32 + mt*16 + r4;
        #pragma unroll
        for (int nt = 0; nt < 8; ++nt) {
            int col = wn*64 + nt*8 + kp;
            sC[rl*PITCH + col]       = c[mt][nt][0];
            sC[rl*PITCH + col + 1]   = c[mt][nt][1];
            sC[(rl+8)*PITCH + col]   = c[mt][nt][2];
            sC[(rl+8)*PITCH + col+1] = c[mt][nt][3];
        }
    }
    __syncthreads();

    // ---- epilogue: 4 threads per row, 64 cols each ----
    int r = tid & 63, q = tid >> 6;
    int pt = m_block + r;
    float* row = sC + r*PITCH + q*64;

    float s = 0.f, ss = 0.f;
    #pragma unroll 8
    for (int j = 0; j < 64; ++j) {
        float v = row[j] + (bias ? bias[q*64 + j] : 0.f);
        row[j] = v;
        s += v; ss += v*v;
    }
    float mu = 0.f, rstd = 0.f;
    if (mode == MODE_LN) {
        sRs[r*4+q] = s; sRss[r*4+q] = ss;
        __syncthreads();
        float S  = sRs[r*4]  + sRs[r*4+1]  + sRs[r*4+2]  + sRs[r*4+3];
        float SS = sRss[r*4] + sRss[r*4+1] + sRss[r*4+2] + sRss[r*4+3];
        mu = S * (1.f/256.f);
        rstd = rsqrtf(SS * (1.f/256.f) - mu*mu + 1e-5f);
    }

    if (mode == MODE_Q) {
        #pragma unroll
        for (int j0 = 0; j0 < 64; j0 += 4) {
            float4 v4 = make_float4(row[j0]*scale, row[j0+1]*scale, row[j0+2]*scale, row[j0+3]*scale);
            *(float4*)(g_Q + (size_t)pt*256 + q*64 + j0) = v4;
        }
    } else {
        float cx = 0.f, cy = 0.f, r2 = 0.f;
        if (mode == MODE_BASIS) { cx = coords[2*pt]; cy = coords[2*pt+1]; r2 = cx*cx + cy*cy; }
        __nv_bfloat16* oH = selH(dst);
        __nv_bfloat16* oL = selL(dst);
        for (int j0 = 0; j0 < 64; j0 += 8) {
            __nv_bfloat16 hb[8], lb[8];
            #pragma unroll
            for (int i = 0; i < 8; ++i) {
                int h = q*64 + j0 + i;
                float v = row[j0 + i];
                if (mode == MODE_LN) v = (v - mu) * rstd * lng[h] + lnb[h];
                else if (mode == MODE_BASIS) {
                    int idx = L*256 + h;
                    float wx = gW[2*idx], wy = gW[2*idx+1];
                    float mx = gmu[2*idx], my = gmu[2*idx+1];
                    float D = r2 + mx*mx + my*my - 2.f*(cx*mx + cy*my);
                    v *= sinf(wx*cx + wy*cy + gb[idx]) * __expf(-0.5f * D * gga[idx]);
                }
                hb[i] = __float2bfloat16_rn(v);
                lb[i] = __float2bfloat16_rn(v - __bfloat162float(hb[i]));
            }
            *(uint4*)(oH + (size_t)pt*256 + q*64 + j0) = *(uint4*)hb;
            *(uint4*)(oL + (size_t)pt*256 + q*64 + j0) = *(uint4*)lb;
        }
    }
}

// ======== attention (scalar, proven R5 structure) ========
#define ATTN_SMF (5120 + P*512)
__global__ void __launch_bounds__(256, 2) attn_kernel() {
    extern __shared__ float smf[];
    float* sA = smf;           // [256][PP] Q staging
    float* sS = sA + 5120;     // [P][512]
    int t = threadIdx.x, lane = t & 31, w = t >> 5;
    int bid = blockIdx.x, b = bid >> 10, n0 = (bid & 1023) * P;
    size_t base = (size_t)(b*NPTS + n0) * 256;
    #pragma unroll
    for (int p = 0; p < P; ++p) sA[t*PP + p] = g_Q[base + (size_t)p*256 + t];
    __syncthreads();
    #pragma unroll
    for (int rep = 0; rep < 2; ++rep) {
        int pair = t + rep*256, hh = pair >> 6, m = pair & 63;
        const float* Kp = &g_Kt[((b*8 + hh)*32)*M_KV + m];
        ull a2[8];
        #pragma unroll
        for (int j = 0; j < 8; ++j) a2[j] = 0ull;
        #pragma unroll 4
        for (int k = 0; k < 32; ++k) {
            float kv = Kp[k*M_KV];
            ull kk = pack2(kv, kv);
            const ulonglong2* col = (const ulonglong2*)(sA + (hh*32 + k)*PP);
            #pragma unroll
            for (int q = 0; q < 4; ++q) { ulonglong2 x = col[q]; fma2(a2[2*q], x.x, kk); fma2(a2[2*q+1], x.y, kk); }
        }
        #pragma unroll
        for (int j = 0; j < 8; ++j) {
            float lo, hi; unpack2(a2[j], lo, hi);
            sS[(2*j)*512 + pair] = lo; sS[(2*j+1)*512 + pair] = hi;
        }
    }
    __syncthreads();
    for (int rr = 0; rr < 16; ++rr) {
        int r = w + rr*8, p = r >> 3, hh = r & 7;
        float* bs = &sS[p*512 + hh*64];
        float v0 = bs[lane], v1 = bs[lane+32];
        float mx = fmaxf(v0, v1);
        #pragma unroll
        for (int o = 16; o; o >>= 1) mx = fmaxf(mx, __shfl_xor_sync(0xffffffffu, mx, o));
        float e0 = __expf(v0-mx), e1 = __expf(v1-mx), sum = e0 + e1;
        #pragma unroll
        for (int o = 16; o; o >>= 1) sum += __shfl_xor_sync(0xffffffffu, sum, o);
        float inv = 1.f/sum;
        bs[lane] = e0*inv; bs[lane+32] = e1*inv;
    }
    __syncthreads();
    {
        int hh = t >> 5;
        ull acc[P];
        #pragma unroll
        for (int p = 0; p < P; ++p) acc[p] = 0ull;
        const float* Vb = g_Vt + b*32*512;
        #pragma unroll 2
        for (int m = 0; m < M_KV; m += 2) {
            ull vv = *(const ull*)(Vb + ((m>>1)*256 + t)*2);
            #pragma unroll
            for (int p = 0; p < P; ++p) fma2(acc[p], *(const ull*)(&sS[p*512 + hh*64 + m]), vv);
        }
        #pragma unroll
        for (int p = 0; p < P; ++p) {
            float v = fold2(acc[p]);
            __nv_bfloat16 h = __float2bfloat16_rn(v);
            g_X0h[base + (size_t)p*256 + t] = h;
            g_X0l[base + (size_t)p*256 + t] = __float2bfloat16_rn(v - __bfloat162float(h));
        }
    }
}

// ======== fin + irfft ========
__global__ void __launch_bounds__(256, 2)
fin_kernel(const float* __restrict__ fin_W, const float* __restrict__ fin_b,
           float* __restrict__ out) {
    __shared__ float sA[256*PP];
    __shared__ float sF[P*36];
    __shared__ float sTab[32];
    int t = threadIdx.x;
    int bid = blockIdx.x, b = bid >> 10, n0 = (bid & 1023) * P;
    size_t base = (size_t)(b*NPTS + n0) * 256;
    if (t < 16) {
        float sv, cv;
        sincosf(0.39269908169872414f * (float)t, &sv, &cv);
        sTab[2*t] = cv; sTab[2*t+1] = sv;
    }
    #pragma unroll
    for (int p = 0; p < P; ++p)
        sA[t*PP + p] = __bfloat162float(g_X0h[base + (size_t)p*256 + t])
                     + __bfloat162float(g_X0l[base + (size_t)p*256 + t]);
    __syncthreads();
    {
        int g = t >> 2, j = t & 3;
        ull part2[8];
        #pragma unroll
        for (int q = 0; q < 8; ++q) part2[q] = 0ull;
        if (g < 36) {
            const float* Wo = &fin_W[g*256];
            #pragma unroll 4
            for (int k = 0; k < 64; ++k) {
                int h = (k << 2) + j;
                float wv = Wo[h];
                ull ww = pack2(wv, wv);
                const ulonglong2* col = (const ulonglong2*)(sA + h*PP);
                #pragma unroll
                for (int q = 0; q < 4; ++q) { ulonglong2 x = col[q]; fma2(part2[2*q], x.x, ww); fma2(part2[2*q+1], x.y, ww); }
            }
        }
        float part[P];
        #pragma unroll
        for (int q = 0; q < 8; ++q) unpack2(part2[q], part[2*q], part[2*q+1]);
        #pragma unroll
        for (int p = 0; p < P; ++p) {
            part[p] += __shfl_xor_sync(0xffffffffu, part[p], 1);
            part[p] += __shfl_xor_sync(0xffffffffu, part[p], 2);
        }
        if (g < 36 && j == 0) {
            float bb = fin_b[g];
            #pragma unroll
            for (int p = 0; p < P; ++p) sF[p*36 + g] = part[p] + bb;
        }
    }
    __syncthreads();
    {
        int inner = t & 31, p = inner >> 1, c = inner & 1;
        const float* Fp = &sF[p*36];
        #pragma unroll
        for (int it = 0; it < 2; ++it) {
            int tt = (t >> 5) + 8*it;
            float a = Fp[c*2];
            float f8 = Fp[8*4 + c*2];
            a += (tt & 1) ? -f8 : f8;
            #pragma unroll
            for (int fq = 1; fq < 8; ++fq) {
                float re = Fp[fq*4 + c*2], im = Fp[fq*4 + c*2 + 1];
                int k = (fq*tt) & 15;
                a += 2.f * (re*sTab[2*k] - im*sTab[2*k+1]);
            }
            out[(((b*16 + tt)*NPTS) + n0 + p)*2 + c] = 0.25f * a;
        }
    }
}

// ======== launch ========
extern "C" void kernel_launch(void* const* d_in, const int* in_sizes, int n_in,
                              void* d_out, int out_size) {
    const float* z_multi=(const float*)d_in[0];  const float* coords=(const float*)d_in[1];
    const float* gabor_W=(const float*)d_in[2];  const float* gabor_b=(const float*)d_in[3];
    const float* gabor_mu=(const float*)d_in[4]; const float* gabor_ga=(const float*)d_in[5];
    const float* net1_W=(const float*)d_in[6];   const float* net1_b=(const float*)d_in[7];
    const float* net2_W=(const float*)d_in[8];   const float* qp_W1=(const float*)d_in[9];
    const float* qp_b1=(const float*)d_in[10];   const float* qp_W2=(const float*)d_in[11];
    const float* qp_b2=(const float*)d_in[12];   const float* in_W=(const float*)d_in[13];
    const float* in_b=(const float*)d_in[14];    const float* out_W=(const float*)d_in[15];
    const float* out_b=(const float*)d_in[16];   const float* lnq_g=(const float*)d_in[17];
    const float* lnq_b=(const float*)d_in[18];   const float* lnkv_g=(const float*)d_in[19];
    const float* lnkv_b=(const float*)d_in[20];  const float* fin_W=(const float*)d_in[21];
    const float* fin_b=(const float*)d_in[22];
    float* out = (float*)d_out;

    cudaFuncSetAttribute(gemm_mma, cudaFuncAttributeMaxDynamicSharedMemorySize, GEMM_SMEM);
    cudaFuncSetAttribute(attn_kernel, cudaFuncAttributeMaxDynamicSharedMemorySize, ATTN_SMF*4);

    conv_w<<<dim3(256,12), 256>>>(qp_W2, in_W, out_W, net2_W, net1_W);
    kv_kernel<<<BATCH*M_KV, 256>>>(z_multi, lnkv_g, lnkv_b, in_W, in_b);
    gelu_kernel<<<TOTM/8, 256>>>(coords, qp_W1, qp_b1);

    int G = TOTM/64;
    const float qscale = 0.17677669529663687f;  // 1/sqrt(32)
    // q = LN(X0 @ qpW2^T + b2) -> X1
    gemm_mma<<<G,256,GEMM_SMEM>>>(MODE_LN,0,1, 0,0, 0,0, 1, qp_b2,1.f, lnq_g,lnq_b, 0,0,0,0, 0);
    // Q = (X1 @ Wq^T + bq)*scale -> g_Q
    gemm_mma<<<G,256,GEMM_SMEM>>>(MODE_Q,0,1, 1,0, 1,0, 0, in_b,qscale, 0,0, 0,0,0,0, 0);
    attn_kernel<<<BATCH*(NPTS/P), 256, ATTN_SMF*4>>>();
    // z = ctx @ outW^T + out_b -> Z2
    gemm_mma<<<G,256,GEMM_SMEM>>>(MODE_BIAS,0,1, 0,0, 2,0, 2, out_b,1.f, 0,0, 0,0,0,0, 0);
    // x = basis0 * (Z2 @ net2[0]^T) -> X0
    gemm_mma<<<G,256,GEMM_SMEM>>>(MODE_BASIS,0,1, 2,0, 3,0, 0, (const float*)0,1.f, 0,0,
                                  gabor_W,gabor_b,gabor_mu,gabor_ga, coords);
    // layers 1..4: x = basis_i * (x @ net1[i-1]^T + net1_b[i-1] + Z2 @ net2[i]^T)
    gemm_mma<<<G,256,GEMM_SMEM>>>(MODE_BASIS,1,2, 0,2, 8,4, 1, net1_b+0,1.f, 0,0,
                                  gabor_W,gabor_b,gabor_mu,gabor_ga, coords);
    gemm_mma<<<G,256,GEMM_SMEM>>>(MODE_BASIS,2,2, 1,2, 9,5, 0, net1_b+256,1.f, 0,0,
                                  gabor_W,gabor_b,gabor_mu,gabor_ga, coords);
    gemm_mma<<<G,256,GEMM_SMEM>>>(MODE_BASIS,3,2, 0,2, 10,6, 1, net1_b+512,1.f, 0,0,
                                  gabor_W,gabor_b,gabor_mu,gabor_ga, coords);
    gemm_mma<<<G,256,GEMM_SMEM>>>(MODE_BASIS,4,2, 1,2, 11,7, 0, net1_b+768,1.f, 0,0,
                                  gabor_W,gabor_b,gabor_mu,gabor_ga, coords);
    fin_kernel<<<BATCH*(NPTS/P), 256>>>(fin_W, fin_b, out);
}

// round 9
// speedup vs baseline: 2.1509x; 2.1509x over previous
#include <cuda_runtime.h>
#include <cuda_bf16.h>
#include <math.h>
#include <stdint.h>

#define BATCH 8
#define NPTS  16384
#define M_KV  64
#define TOTM  (BATCH*NPTS)
#define P     16
#define PP    20
#define PITCH 257
typedef unsigned long long ull;

// ======== PTX helpers ========
__device__ __forceinline__ uint32_t smem_u32(const void* p) {
    uint32_t a;
    asm("{ .reg .u64 t; cvta.to.shared.u64 t, %1; cvt.u32.u64 %0, t; }" : "=r"(a) : "l"(p));
    return a;
}
#define CP16(dst, src) asm volatile("cp.async.cg.shared.global [%0], [%1], 16;" :: "r"(dst), "l"(src) : "memory")
#define CP_COMMIT()    asm volatile("cp.async.commit_group;" ::: "memory")
#define CP_WAIT1()     asm volatile("cp.async.wait_group 1;" ::: "memory")
#define CP_WAIT0()     asm volatile("cp.async.wait_group 0;" ::: "memory")
__device__ __forceinline__ void ldsm4(uint32_t* r, uint32_t addr) {
    asm volatile("ldmatrix.sync.aligned.m8n8.x4.shared.b16 {%0,%1,%2,%3}, [%4];"
        : "=r"(r[0]), "=r"(r[1]), "=r"(r[2]), "=r"(r[3]) : "r"(addr));
}
__device__ __forceinline__ void mma16816(float* c, const uint32_t* a, uint32_t b0, uint32_t b1) {
    asm volatile("mma.sync.aligned.m16n8k16.row.col.f32.bf16.bf16.f32 "
        "{%0,%1,%2,%3}, {%4,%5,%6,%7}, {%8,%9}, {%0,%1,%2,%3};"
        : "+f"(c[0]), "+f"(c[1]), "+f"(c[2]), "+f"(c[3])
        : "r"(a[0]), "r"(a[1]), "r"(a[2]), "r"(a[3]), "r"(b0), "r"(b1));
}
__device__ __forceinline__ void fma2(ull& a, ull x, ull w) {
    asm("fma.rn.f32x2 %0, %1, %2, %0;" : "+l"(a) : "l"(x), "l"(w));
}
__device__ __forceinline__ float fold2(ull v) { float lo,hi; asm("mov.b64 {%0,%1}, %2;" : "=f"(lo),"=f"(hi) : "l"(v)); return lo+hi; }
__device__ __forceinline__ void unpack2(ull v, float& lo, float& hi) { asm("mov.b64 {%0,%1}, %2;" : "=f"(lo),"=f"(hi) : "l"(v)); }
__device__ __forceinline__ ull pack2(float lo, float hi) { ull r; asm("mov.b64 %0, {%1,%2};" : "=l"(r) : "f"(lo),"f"(hi)); return r; }

// ======== global scratch ========
#define SZ ((size_t)TOTM * 256)
__device__ __nv_bfloat16 g_X0h[SZ], g_X0l[SZ], g_X1h[SZ], g_X1l[SZ], g_Z2h[SZ], g_Z2l[SZ];
__device__ float g_Q[SZ];
__device__ __nv_bfloat16 g_Bh[12*65536], g_Bl[12*65536];
__device__ float g_Kt[BATCH*8*32*M_KV];
__device__ float g_Vt[BATCH*32*256*2];
__device__ __forceinline__ __nv_bfloat16* selH(int s){ return s==0?g_X0h:(s==1?g_X1h:g_Z2h); }
__device__ __forceinline__ __nv_bfloat16* selL(int s){ return s==0?g_X0l:(s==1?g_X1l:g_Z2l); }

// ======== prep kernels ========
__global__ void conv_w(const float* __restrict__ qp_W2, const float* __restrict__ in_W,
                       const float* __restrict__ out_W, const float* __restrict__ net2_W,
                       const float* __restrict__ net1_W) {
    int n = blockIdx.x, mat = blockIdx.y, k = threadIdx.x;
    const float* src;
    switch (mat) {
        case 0: src = qp_W2; break;
        case 1: src = in_W;  break;
        case 2: src = out_W; break;
        default: src = (mat < 8) ? net2_W + (mat-3)*65536 : net1_W + (mat-8)*65536;
    }
    float w = src[n*256 + k];
    __nv_bfloat16 h = __float2bfloat16_rn(w);
    g_Bh[mat*65536 + n*256 + k] = h;
    g_Bl[mat*65536 + n*256 + k] = __float2bfloat16_rn(w - __bfloat162float(h));
}

__global__ void kv_kernel(const float* __restrict__ z_multi,
                          const float* __restrict__ lnkv_g, const float* __restrict__ lnkv_b,
                          const float* __restrict__ in_W,  const float* __restrict__ in_b) {
    __shared__ float kvn[256], rs[8], rss[8];
    __shared__ float s_mu, s_rstd;
    int row = blockIdx.x, b = row >> 6, m = row & 63;
    int t = threadIdx.x, lane = t & 31, w = t >> 5;
    float v = z_multi[row*256 + t];
    float s = v, ss = v*v;
    #pragma unroll
    for (int o = 16; o; o >>= 1) {
        s  += __shfl_xor_sync(0xffffffffu, s,  o);
        ss += __shfl_xor_sync(0xffffffffu, ss, o);
    }
    if (lane == 0) { rs[w] = s; rss[w] = ss; }
    __syncthreads();
    if (t == 0) {
        float S=0.f, SS=0.f;
        for (int i = 0; i < 8; ++i) { S += rs[i]; SS += rss[i]; }
        float mu = S*(1.f/256.f);
        s_mu = mu; s_rstd = rsqrtf(SS*(1.f/256.f) - mu*mu + 1e-5f);
    }
    __syncthreads();
    kvn[t] = (v - s_mu) * s_rstd * lnkv_g[t] + lnkv_b[t];
    __syncthreads();
    float aK = in_b[256+t], aV = in_b[512+t];
    const float* wk = in_W + (size_t)(256+t)*256;
    const float* wv = in_W + (size_t)(512+t)*256;
    #pragma unroll 4
    for (int d = 0; d < 256; ++d) { float x = kvn[d]; aK += x*wk[d]; aV += x*wv[d]; }
    g_Kt[((b*8 + (t>>5))*32 + (t&31))*M_KV + m] = aK;
    g_Vt[((b*32 + (m>>1))*256 + t)*2 + (m&1)] = aV;
}

__global__ void gelu_kernel(const float* __restrict__ coords,
                            const float* __restrict__ qp_W1, const float* __restrict__ qp_b1) {
    int t = threadIdx.x;
    int pt0 = blockIdx.x * 8;
    float wx = qp_W1[2*t], wy = qp_W1[2*t+1], bb = qp_b1[t];
    #pragma unroll
    for (int p = 0; p < 8; ++p) {
        int pt = pt0 + p;
        float u = wx*coords[2*pt] + wy*coords[2*pt+1] + bb;
        float v = 0.5f*u*(1.f + erff(u*0.70710678118654752f));
        __nv_bfloat16 h = __float2bfloat16_rn(v);
        g_X0h[(size_t)pt*256 + t] = h;
        g_X0l[(size_t)pt*256 + t] = __float2bfloat16_rn(v - __bfloat162float(h));
    }
}

// ======== warp-MMA GEMM, cp.async + ldmatrix pipeline ========
// C[64 x 256] = sum_s A_s[64 x 256] @ B_s^T, bf16 split-3, fp32 accum.
// 8 warps: wm = w>>2 (M half), wn = w&3 (N quarter); warp tile m32 x n64.
// smem buffer (bytes): Ah[64x40]=5120 | Al=5120 | Bh[256x40]=20480 | Bl=20480  => 51200/buf, x2
#define BUF_BYTES 51200u
#define OFF_AL 5120u
#define OFF_BH 10240u
#define OFF_BL 30720u
#define GEMM_SMEM (2*51200)
#define MODE_LN 0
#define MODE_Q 1
#define MODE_BIAS 2
#define MODE_BASIS 3

__device__ __forceinline__ void load_chunk(uint32_t base, const __nv_bfloat16* AH, const __nv_bfloat16* AL,
                                           const __nv_bfloat16* BH, const __nv_bfloat16* BL,
                                           int m0, int c, int tid) {
    int r = tid >> 2, seg = tid & 3;
    size_t gofs = (size_t)r*256 + c*32 + seg*8;
    uint32_t sA = base + (uint32_t)(r*80 + seg*16);
    CP16(sA, AH + (size_t)m0*256 + gofs);
    CP16(sA + OFF_AL, AL + (size_t)m0*256 + gofs);
    #pragma unroll
    for (int it = 0; it < 4; ++it) {
        uint32_t sB = base + OFF_BH + (uint32_t)((r + it*64)*80 + seg*16);
        CP16(sB, BH + (size_t)it*64*256 + gofs);
        CP16(sB + 20480u, BL + (size_t)it*64*256 + gofs);
    }
}

__global__ void __launch_bounds__(256, 2)
gemm_mma(int mode, int L, int nsrc, int srcA1, int srcA2, int matB1, int matB2, int dst,
         const float* __restrict__ bias, float scale,
         const float* __restrict__ lng, const float* __restrict__ lnb,
         const float* __restrict__ gW, const float* __restrict__ gb,
         const float* __restrict__ gmu, const float* __restrict__ gga,
         const float* __restrict__ coords) {
    extern __shared__ char smraw[];
    uint32_t sb = smem_u32(smraw);
    int tid = threadIdx.x, lane = tid & 31, w = tid >> 5;
    int wn = w & 3, wm = w >> 2;
    int m_block = blockIdx.x * 64;

    const __nv_bfloat16* AHs[2] = { selH(srcA1), selH(srcA2) };
    const __nv_bfloat16* ALs[2] = { selL(srcA1), selL(srcA2) };
    const __nv_bfloat16* BHs[2] = { g_Bh + (size_t)matB1*65536, g_Bh + (size_t)matB2*65536 };
    const __nv_bfloat16* BLs[2] = { g_Bl + (size_t)matB1*65536, g_Bl + (size_t)matB2*65536 };

    // per-lane ldmatrix offsets
    int sub = lane & 7, blk = lane >> 3;
    int rowoff = sub + ((blk & 1) << 3);       // 0..15
    int koff = (blk >> 1) << 3;                // 0 or 8
    uint32_t aoff[2][2], boff[4][2];
    #pragma unroll
    for (int mt = 0; mt < 2; ++mt)
        #pragma unroll
        for (int kh = 0; kh < 2; ++kh)
            aoff[mt][kh] = (uint32_t)(((wm*32 + mt*16 + rowoff)*40 + kh*16 + koff) * 2);
    #pragma unroll
    for (int ng = 0; ng < 4; ++ng)
        #pragma unroll
        for (int kh = 0; kh < 2; ++kh)
            boff[ng][kh] = (uint32_t)(((wn*64 + ng*16 + rowoff)*40 + kh*16 + koff) * 2);

    float c[2][8][4];
    #pragma unroll
    for (int mt = 0; mt < 2; ++mt)
        #pragma unroll
        for (int nt = 0; nt < 8; ++nt)
            #pragma unroll
            for (int i = 0; i < 4; ++i) c[mt][nt][i] = 0.f;

    int total = nsrc * 8;
    load_chunk(sb, AHs[0], ALs[0], BHs[0], BLs[0], m_block, 0, tid);
    CP_COMMIT();

    for (int ch = 0; ch < total; ++ch) {
        if (ch + 1 < total) {
            int s = (ch+1) >> 3;
            load_chunk(sb + ((ch+1)&1)*BUF_BYTES, AHs[s], ALs[s], BHs[s], BLs[s],
                       m_block, (ch+1)&7, tid);
            CP_COMMIT();
            CP_WAIT1();
        } else {
            CP_WAIT0();
        }
        __syncthreads();
        uint32_t base = sb + (ch&1)*BUF_BYTES;
        uint32_t ah[2][2][4], al[2][2][4];
        #pragma unroll
        for (int mt = 0; mt < 2; ++mt)
            #pragma unroll
            for (int kh = 0; kh < 2; ++kh) {
                ldsm4(ah[mt][kh], base + aoff[mt][kh]);
                ldsm4(al[mt][kh], base + OFF_AL + aoff[mt][kh]);
            }
        #pragma unroll
        for (int kh = 0; kh < 2; ++kh) {
            #pragma unroll
            for (int ng = 0; ng < 4; ++ng) {
                uint32_t bh[4], bl[4];
                ldsm4(bh, base + OFF_BH + boff[ng][kh]);
                #pragma unroll
                for (int mt = 0; mt < 2; ++mt) {
                    mma16816(c[mt][2*ng],   ah[mt][kh], bh[0], bh[2]);
                    mma16816(c[mt][2*ng+1], ah[mt][kh], bh[1], bh[3]);
                    mma16816(c[mt][2*ng],   al[mt][kh], bh[0], bh[2]);
                    mma16816(c[mt][2*ng+1], al[mt][kh], bh[1], bh[3]);
                }
                ldsm4(bl, base + OFF_BL + boff[ng][kh]);
                #pragma unroll
                for (int mt = 0; mt < 2; ++mt) {
                    mma16816(c[mt][2*ng],   ah[mt][kh], bl[0], bl[2]);
                    mma16816(c[mt][2*ng+1], ah[mt][kh], bl[1], bl[3]);
                }
            }
        }
        __syncthreads();
    }

    // ---- epilogue: alias smem as float C[64][PITCH] + reduce scratch ----
    float* sC = (float*)smraw;
    float* sRs  = sC + 64*PITCH;
    float* sRss = sRs + 256;
    int r4 = lane >> 2, kp = (lane & 3) * 2;
    #pragma unroll
    for (int mt = 0; mt < 2; ++mt) {
        int rl = wm*32 + mt*16 + r4;
        #pragma unroll
        for (int nt = 0; nt < 8; ++nt) {
            int col = wn*64 + nt*8 + kp;
            sC[rl*PITCH + col]       = c[mt][nt][0];
            sC[rl*PITCH + col + 1]   = c[mt][nt][1];
            sC[(rl+8)*PITCH + col]   = c[mt][nt][2];
            sC[(rl+8)*PITCH + col+1] = c[mt][nt][3];
        }
    }
    __syncthreads();

    int r = tid & 63, q = tid >> 6;
    int pt = m_block + r;
    float* row = sC + r*PITCH + q*64;

    float s = 0.f, ss = 0.f;
    #pragma unroll 8
    for (int j = 0; j < 64; ++j) {
        float v = row[j] + (bias ? bias[q*64 + j] : 0.f);
        row[j] = v;
        s += v; ss += v*v;
    }
    float mu = 0.f, rstd = 0.f;
    if (mode == MODE_LN) {
        sRs[r*4+q] = s; sRss[r*4+q] = ss;
        __syncthreads();
        float S  = sRs[r*4]  + sRs[r*4+1]  + sRs[r*4+2]  + sRs[r*4+3];
        float SS = sRss[r*4] + sRss[r*4+1] + sRss[r*4+2] + sRss[r*4+3];
        mu = S * (1.f/256.f);
        rstd = rsqrtf(SS * (1.f/256.f) - mu*mu + 1e-5f);
    }

    if (mode == MODE_Q) {
        #pragma unroll
        for (int j0 = 0; j0 < 64; j0 += 4) {
            float4 v4 = make_float4(row[j0]*scale, row[j0+1]*scale, row[j0+2]*scale, row[j0+3]*scale);
            *(float4*)(g_Q + (size_t)pt*256 + q*64 + j0) = v4;
        }
    } else {
        float cx = 0.f, cy = 0.f, r2 = 0.f;
        if (mode == MODE_BASIS) { cx = coords[2*pt]; cy = coords[2*pt+1]; r2 = cx*cx + cy*cy; }
        __nv_bfloat16* oH = selH(dst);
        __nv_bfloat16* oL = selL(dst);
        for (int j0 = 0; j0 < 64; j0 += 8) {
            __nv_bfloat16 hb[8], lb[8];
            #pragma unroll
            for (int i = 0; i < 8; ++i) {
                int h = q*64 + j0 + i;
                float v = row[j0 + i];
                if (mode == MODE_LN) v = (v - mu) * rstd * lng[h] + lnb[h];
                else if (mode == MODE_BASIS) {
                    int idx = L*256 + h;
                    float wx = gW[2*idx], wy = gW[2*idx+1];
                    float mx = gmu[2*idx], my = gmu[2*idx+1];
                    float D = r2 + mx*mx + my*my - 2.f*(cx*mx + cy*my);
                    v *= sinf(wx*cx + wy*cy + gb[idx]) * __expf(-0.5f * D * gga[idx]);
                }
                hb[i] = __float2bfloat16_rn(v);
                lb[i] = __float2bfloat16_rn(v - __bfloat162float(hb[i]));
            }
            *(uint4*)(oH + (size_t)pt*256 + q*64 + j0) = *(uint4*)hb;
            *(uint4*)(oL + (size_t)pt*256 + q*64 + j0) = *(uint4*)lb;
        }
    }
}

// ======== attention (scalar) ========
#define ATTN_SMF (5120 + P*512)
__global__ void __launch_bounds__(256, 2) attn_kernel() {
    extern __shared__ float smf[];
    float* sA = smf;
    float* sS = sA + 5120;
    int t = threadIdx.x, lane = t & 31, w = t >> 5;
    int bid = blockIdx.x, b = bid >> 10, n0 = (bid & 1023) * P;
    size_t base = (size_t)(b*NPTS + n0) * 256;
    #pragma unroll
    for (int p = 0; p < P; ++p) sA[t*PP + p] = g_Q[base + (size_t)p*256 + t];
    __syncthreads();
    #pragma unroll
    for (int rep = 0; rep < 2; ++rep) {
        int pair = t + rep*256, hh = pair >> 6, m = pair & 63;
        const float* Kp = &g_Kt[((b*8 + hh)*32)*M_KV + m];
        ull a2[8];
        #pragma unroll
        for (int j = 0; j < 8; ++j) a2[j] = 0ull;
        #pragma unroll 4
        for (int k = 0; k < 32; ++k) {
            float kv = Kp[k*M_KV];
            ull kk = pack2(kv, kv);
            const ulonglong2* col = (const ulonglong2*)(sA + (hh*32 + k)*PP);
            #pragma unroll
            for (int q = 0; q < 4; ++q) { ulonglong2 x = col[q]; fma2(a2[2*q], x.x, kk); fma2(a2[2*q+1], x.y, kk); }
        }
        #pragma unroll
        for (int j = 0; j < 8; ++j) {
            float lo, hi; unpack2(a2[j], lo, hi);
            sS[(2*j)*512 + pair] = lo; sS[(2*j+1)*512 + pair] = hi;
        }
    }
    __syncthreads();
    for (int rr = 0; rr < 16; ++rr) {
        int r = w + rr*8, p = r >> 3, hh = r & 7;
        float* bs = &sS[p*512 + hh*64];
        float v0 = bs[lane], v1 = bs[lane+32];
        float mx = fmaxf(v0, v1);
        #pragma unroll
        for (int o = 16; o; o >>= 1) mx = fmaxf(mx, __shfl_xor_sync(0xffffffffu, mx, o));
        float e0 = __expf(v0-mx), e1 = __expf(v1-mx), sum = e0 + e1;
        #pragma unroll
        for (int o = 16; o; o >>= 1) sum += __shfl_xor_sync(0xffffffffu, sum, o);
        float inv = 1.f/sum;
        bs[lane] = e0*inv; bs[lane+32] = e1*inv;
    }
    __syncthreads();
    {
        int hh = t >> 5;
        ull acc[P];
        #pragma unroll
        for (int p = 0; p < P; ++p) acc[p] = 0ull;
        const float* Vb = g_Vt + b*32*512;
        #pragma unroll 2
        for (int m = 0; m < M_KV; m += 2) {
            ull vv = *(const ull*)(Vb + ((m>>1)*256 + t)*2);
            #pragma unroll
            for (int p = 0; p < P; ++p) fma2(acc[p], *(const ull*)(&sS[p*512 + hh*64 + m]), vv);
        }
        #pragma unroll
        for (int p = 0; p < P; ++p) {
            float v = fold2(acc[p]);
            __nv_bfloat16 h = __float2bfloat16_rn(v);
            g_X0h[base + (size_t)p*256 + t] = h;
            g_X0l[base + (size_t)p*256 + t] = __float2bfloat16_rn(v - __bfloat162float(h));
        }
    }
}

// ======== fin + irfft ========
__global__ void __launch_bounds__(256, 2)
fin_kernel(const float* __restrict__ fin_W, const float* __restrict__ fin_b,
           float* __restrict__ out) {
    __shared__ float sA[256*PP];
    __shared__ float sF[P*36];
    __shared__ float sTab[32];
    int t = threadIdx.x;
    int bid = blockIdx.x, b = bid >> 10, n0 = (bid & 1023) * P;
    size_t base = (size_t)(b*NPTS + n0) * 256;
    if (t < 16) {
        float sv, cv;
        sincosf(0.39269908169872414f * (float)t, &sv, &cv);
        sTab[2*t] = cv; sTab[2*t+1] = sv;
    }
    #pragma unroll
    for (int p = 0; p < P; ++p)
        sA[t*PP + p] = __bfloat162float(g_X0h[base + (size_t)p*256 + t])
                     + __bfloat162float(g_X0l[base + (size_t)p*256 + t]);
    __syncthreads();
    {
        int g = t >> 2, j = t & 3;
        ull part2[8];
        #pragma unroll
        for (int q = 0; q < 8; ++q) part2[q] = 0ull;
        if (g < 36) {
            const float* Wo = &fin_W[g*256];
            #pragma unroll 4
            for (int k = 0; k < 64; ++k) {
                int h = (k << 2) + j;
                float wv = Wo[h];
                ull ww = pack2(wv, wv);
                const ulonglong2* col = (const ulonglong2*)(sA + h*PP);
                #pragma unroll
                for (int q = 0; q < 4; ++q) { ulonglong2 x = col[q]; fma2(part2[2*q], x.x, ww); fma2(part2[2*q+1], x.y, ww); }
            }
        }
        float part[P];
        #pragma unroll
        for (int q = 0; q < 8; ++q) unpack2(part2[q], part[2*q], part[2*q+1]);
        #pragma unroll
        for (int p = 0; p < P; ++p) {
            part[p] += __shfl_xor_sync(0xffffffffu, part[p], 1);
            part[p] += __shfl_xor_sync(0xffffffffu, part[p], 2);
        }
        if (g < 36 && j == 0) {
            float bb = fin_b[g];
            #pragma unroll
            for (int p = 0; p < P; ++p) sF[p*36 + g] = part[p] + bb;
        }
    }
    __syncthreads();
    {
        int inner = t & 31, p = inner >> 1, c = inner & 1;
        const float* Fp = &sF[p*36];
        #pragma unroll
        for (int it = 0; it < 2; ++it) {
            int tt = (t >> 5) + 8*it;
            float a = Fp[c*2];
            float f8 = Fp[8*4 + c*2];
            a += (tt & 1) ? -f8 : f8;
            #pragma unroll
            for (int fq = 1; fq < 8; ++fq) {
                float re = Fp[fq*4 + c*2], im = Fp[fq*4 + c*2 + 1];
                int k = (fq*tt) & 15;
                a += 2.f * (re*sTab[2*k] - im*sTab[2*k+1]);
            }
            out[(((b*16 + tt)*NPTS) + n0 + p)*2 + c] = 0.25f * a;
        }
    }
}

// ======== launch ========
extern "C" void kernel_launch(void* const* d_in, const int* in_sizes, int n_in,
                              void* d_out, int out_size) {
    const float* z_multi=(const float*)d_in[0];  const float* coords=(const float*)d_in[1];
    const float* gabor_W=(const float*)d_in[2];  const float* gabor_b=(const float*)d_in[3];
    const float* gabor_mu=(const float*)d_in[4]; const float* gabor_ga=(const float*)d_in[5];
    const float* net1_W=(const float*)d_in[6];   const float* net1_b=(const float*)d_in[7];
    const float* net2_W=(const float*)d_in[8];   const float* qp_W1=(const float*)d_in[9];
    const float* qp_b1=(const float*)d_in[10];   const float* qp_W2=(const float*)d_in[11];
    const float* qp_b2=(const float*)d_in[12];   const float* in_W=(const float*)d_in[13];
    const float* in_b=(const float*)d_in[14];    const float* out_W=(const float*)d_in[15];
    const float* out_b=(const float*)d_in[16];   const float* lnq_g=(const float*)d_in[17];
    const float* lnq_b=(const float*)d_in[18];   const float* lnkv_g=(const float*)d_in[19];
    const float* lnkv_b=(const float*)d_in[20];  const float* fin_W=(const float*)d_in[21];
    const float* fin_b=(const float*)d_in[22];
    float* out = (float*)d_out;

    cudaFuncSetAttribute(gemm_mma, cudaFuncAttributeMaxDynamicSharedMemorySize, GEMM_SMEM);
    cudaFuncSetAttribute(attn_kernel, cudaFuncAttributeMaxDynamicSharedMemorySize, ATTN_SMF*4);

    conv_w<<<dim3(256,12), 256>>>(qp_W2, in_W, out_W, net2_W, net1_W);
    kv_kernel<<<BATCH*M_KV, 256>>>(z_multi, lnkv_g, lnkv_b, in_W, in_b);
    gelu_kernel<<<TOTM/8, 256>>>(coords, qp_W1, qp_b1);

    int G = TOTM/64;
    const float qscale = 0.17677669529663687f;  // 1/sqrt(32)
    gemm_mma<<<G,256,GEMM_SMEM>>>(MODE_LN,0,1, 0,0, 0,0, 1, qp_b2,1.f, lnq_g,lnq_b, 0,0,0,0, 0);
    gemm_mma<<<G,256,GEMM_SMEM>>>(MODE_Q,0,1, 1,0, 1,0, 0, in_b,qscale, 0,0, 0,0,0,0, 0);
    attn_kernel<<<BATCH*(NPTS/P), 256, ATTN_SMF*4>>>();
    gemm_mma<<<G,256,GEMM_SMEM>>>(MODE_BIAS,0,1, 0,0, 2,0, 2, out_b,1.f, 0,0, 0,0,0,0, 0);
    gemm_mma<<<G,256,GEMM_SMEM>>>(MODE_BASIS,0,1, 2,0, 3,0, 0, (const float*)0,1.f, 0,0,
                                  gabor_W,gabor_b,gabor_mu,gabor_ga, coords);
    gemm_mma<<<G,256,GEMM_SMEM>>>(MODE_BASIS,1,2, 0,2, 8,4, 1, net1_b+0,1.f, 0,0,
                                  gabor_W,gabor_b,gabor_mu,gabor_ga, coords);
    gemm_mma<<<G,256,GEMM_SMEM>>>(MODE_BASIS,2,2, 1,2, 9,5, 0, net1_b+256,1.f, 0,0,
                                  gabor_W,gabor_b,gabor_mu,gabor_ga, coords);
    gemm_mma<<<G,256,GEMM_SMEM>>>(MODE_BASIS,3,2, 0,2, 10,6, 1, net1_b+512,1.f, 0,0,
                                  gabor_W,gabor_b,gabor_mu,gabor_ga, coords);
    gemm_mma<<<G,256,GEMM_SMEM>>>(MODE_BASIS,4,2, 1,2, 11,7, 0, net1_b+768,1.f, 0,0,
                                  gabor_W,gabor_b,gabor_mu,gabor_ga, coords);
    fin_kernel<<<BATCH*(NPTS/P), 256>>>(fin_W, fin_b, out);
}

// round 10
// speedup vs baseline: 2.3238x; 1.0804x over previous
#include <cuda_runtime.h>
#include <cuda_bf16.h>
#include <math.h>
#include <stdint.h>

#define BATCH 8
#define NPTS  16384
#define M_KV  64
#define TOTM  (BATCH*NPTS)
#define P     16
#define PP    20
typedef unsigned long long ull;

// ======== PTX helpers ========
__device__ __forceinline__ uint32_t smem_u32(const void* p) {
    uint32_t a;
    asm("{ .reg .u64 t; cvta.to.shared.u64 t, %1; cvt.u32.u64 %0, t; }" : "=r"(a) : "l"(p));
    return a;
}
#define CP16(dst, src) asm volatile("cp.async.cg.shared.global [%0], [%1], 16;" :: "r"(dst), "l"(src) : "memory")
#define CP_COMMIT()    asm volatile("cp.async.commit_group;" ::: "memory")
#define CP_WAIT1()     asm volatile("cp.async.wait_group 1;" ::: "memory")
#define CP_WAIT0()     asm volatile("cp.async.wait_group 0;" ::: "memory")
__device__ __forceinline__ void ldsm4(uint32_t* r, uint32_t addr) {
    asm volatile("ldmatrix.sync.aligned.m8n8.x4.shared.b16 {%0,%1,%2,%3}, [%4];"
        : "=r"(r[0]), "=r"(r[1]), "=r"(r[2]), "=r"(r[3]) : "r"(addr));
}
__device__ __forceinline__ void mma16816(float* c, const uint32_t* a, uint32_t b0, uint32_t b1) {
    asm volatile("mma.sync.aligned.m16n8k16.row.col.f32.bf16.bf16.f32 "
        "{%0,%1,%2,%3}, {%4,%5,%6,%7}, {%8,%9}, {%0,%1,%2,%3};"
        : "+f"(c[0]), "+f"(c[1]), "+f"(c[2]), "+f"(c[3])
        : "r"(a[0]), "r"(a[1]), "r"(a[2]), "r"(a[3]), "r"(b0), "r"(b1));
}
#define SW64(o) ((o) ^ (((o) >> 3) & 0x30))
__device__ __forceinline__ void fma2(ull& a, ull x, ull w) {
    asm("fma.rn.f32x2 %0, %1, %2, %0;" : "+l"(a) : "l"(x), "l"(w));
}
__device__ __forceinline__ float fold2(ull v) { float lo,hi; asm("mov.b64 {%0,%1}, %2;" : "=f"(lo),"=f"(hi) : "l"(v)); return lo+hi; }
__device__ __forceinline__ void unpack2(ull v, float& lo, float& hi) { asm("mov.b64 {%0,%1}, %2;" : "=f"(lo),"=f"(hi) : "l"(v)); }
__device__ __forceinline__ ull pack2(float lo, float hi) { ull r; asm("mov.b64 %0, {%1,%2};" : "=l"(r) : "f"(lo),"f"(hi)); return r; }

// ======== global scratch ========
#define SZ ((size_t)TOTM * 256)
__device__ __nv_bfloat16 g_X0h[SZ], g_X0l[SZ], g_X1h[SZ], g_X1l[SZ], g_Z2h[SZ], g_Z2l[SZ];
__device__ float g_Q[SZ];
__device__ __nv_bfloat16 g_Bh[12*65536], g_Bl[12*65536];
__device__ float g_WkT[65536], g_WvT[65536];     // fp32 transposed K/V weights
__device__ float g_Kt[BATCH*8*32*M_KV];
__device__ float g_Vt[BATCH*32*256*2];
__device__ __forceinline__ __nv_bfloat16* selH(int s){ return s==0?g_X0h:(s==1?g_X1h:g_Z2h); }
__device__ __forceinline__ __nv_bfloat16* selL(int s){ return s==0?g_X0l:(s==1?g_X1l:g_Z2l); }

// ======== prep kernels ========
__global__ void conv_w(const float* __restrict__ qp_W2, const float* __restrict__ in_W,
                       const float* __restrict__ out_W, const float* __restrict__ net2_W,
                       const float* __restrict__ net1_W) {
    int n = blockIdx.x, mat = blockIdx.y, k = threadIdx.x;
    if (mat >= 12) {   // fp32 transposes of Wk, Wv
        const float* src = in_W + (size_t)(mat == 12 ? 256 : 512) * 256;
        float* dst = (mat == 12) ? g_WkT : g_WvT;
        dst[k*256 + n] = src[n*256 + k];
        return;
    }
    const float* src;
    switch (mat) {
        case 0: src = qp_W2; break;
        case 1: src = in_W;  break;
        case 2: src = out_W; break;
        default: src = (mat < 8) ? net2_W + (mat-3)*65536 : net1_W + (mat-8)*65536;
    }
    float w = src[n*256 + k];
    __nv_bfloat16 h = __float2bfloat16_rn(w);
    g_Bh[mat*65536 + n*256 + k] = h;
    g_Bl[mat*65536 + n*256 + k] = __float2bfloat16_rn(w - __bfloat162float(h));
}

// 64 blocks x 256 threads; each block: 8 KV rows
__global__ void kv_kernel(const float* __restrict__ z_multi,
                          const float* __restrict__ lnkv_g, const float* __restrict__ lnkv_b,
                          const float* __restrict__ in_b) {
    __shared__ float kvn[8][256];
    int t = threadIdx.x, lane = t & 31, w = t >> 5;
    int row0 = blockIdx.x * 8;
    // warp w normalizes row row0+w
    {
        int row = row0 + w;
        float v[8];
        float s = 0.f, ss = 0.f;
        #pragma unroll
        for (int j = 0; j < 8; ++j) {
            v[j] = z_multi[(size_t)row*256 + lane*8 + j];
            s += v[j]; ss += v[j]*v[j];
        }
        #pragma unroll
        for (int o = 16; o; o >>= 1) {
            s  += __shfl_xor_sync(0xffffffffu, s,  o);
            ss += __shfl_xor_sync(0xffffffffu, ss, o);
        }
        float mu = s * (1.f/256.f);
        float rstd = rsqrtf(ss * (1.f/256.f) - mu*mu + 1e-5f);
        #pragma unroll
        for (int j = 0; j < 8; ++j) {
            int d = lane*8 + j;
            kvn[w][d] = (v[j] - mu) * rstd * lnkv_g[d] + lnkv_b[d];
        }
    }
    __syncthreads();
    float aK[8], aV[8];
    float bK = in_b[256+t], bV = in_b[512+t];
    #pragma unroll
    for (int i = 0; i < 8; ++i) { aK[i] = bK; aV[i] = bV; }
    #pragma unroll 4
    for (int d = 0; d < 256; ++d) {
        float wk = g_WkT[d*256 + t];
        float wv = g_WvT[d*256 + t];
        #pragma unroll
        for (int i = 0; i < 8; ++i) {
            float x = kvn[i][d];
            aK[i] += x * wk;
            aV[i] += x * wv;
        }
    }
    #pragma unroll
    for (int i = 0; i < 8; ++i) {
        int row = row0 + i, b = row >> 6, m = row & 63;
        g_Kt[((b*8 + (t>>5))*32 + (t&31))*M_KV + m] = aK[i];
        g_Vt[((b*32 + (m>>1))*256 + t)*2 + (m&1)] = aV[i];
    }
}

__global__ void gelu_kernel(const float* __restrict__ coords,
                            const float* __restrict__ qp_W1, const float* __restrict__ qp_b1) {
    int t = threadIdx.x;
    int pt0 = blockIdx.x * 8;
    float wx = qp_W1[2*t], wy = qp_W1[2*t+1], bb = qp_b1[t];
    #pragma unroll
    for (int p = 0; p < 8; ++p) {
        int pt = pt0 + p;
        float u = wx*coords[2*pt] + wy*coords[2*pt+1] + bb;
        float v = 0.5f*u*(1.f + erff(u*0.70710678118654752f));
        __nv_bfloat16 h = __float2bfloat16_rn(v);
        g_X0h[(size_t)pt*256 + t] = h;
        g_X0l[(size_t)pt*256 + t] = __float2bfloat16_rn(v - __bfloat162float(h));
    }
}

// ======== warp-MMA GEMM: M128 x N256, K32 chunks, 3-stage cp.async, SW64 smem ========
// buffer: Ah[128x64B]=8K | Al=8K | Bh[256x64B]=16K | Bl=16K -> 48KB; x3 stages
#define OFF_AL 8192u
#define OFF_BH 16384u
#define OFF_BL 32768u
#define BUF_BYTES 49152u
#define GEMM_SMEM (3*49152)
#define MODE_LN 0
#define MODE_Q 1
#define MODE_BIAS 2
#define MODE_BASIS 3

__device__ __forceinline__ void load_chunk(uint32_t base,
        const __nv_bfloat16* AH, const __nv_bfloat16* AL,
        const __nv_bfloat16* BH, const __nv_bfloat16* BL,
        int m0, int c, int tid) {
    int r = tid >> 2, seg = tid & 3;
    size_t aofs = (size_t)(m0 + r)*256 + c*32 + seg*8;
    uint32_t sA = base + SW64((uint32_t)(r*64 + seg*16));
    CP16(sA, AH + aofs);
    CP16(sA + OFF_AL, AL + aofs);
    #pragma unroll
    for (int it = 0; it < 2; ++it) {
        int row = r + it*128;
        size_t bofs = (size_t)row*256 + c*32 + seg*8;
        uint32_t sB = base + OFF_BH + SW64((uint32_t)(row*64 + seg*16));
        CP16(sB, BH + bofs);
        CP16(sB + 16384u, BL + bofs);
    }
}

__global__ void __launch_bounds__(512, 1)
gemm_mma(int mode, int L, int nsrc, int srcA1, int srcA2, int matB1, int matB2, int dst,
         const float* __restrict__ bias, float scale,
         const float* __restrict__ lng, const float* __restrict__ lnb,
         const float* __restrict__ gW, const float* __restrict__ gb,
         const float* __restrict__ gmu, const float* __restrict__ gga,
         const float* __restrict__ coords) {
    extern __shared__ char smraw[];
    uint32_t sb = smem_u32(smraw);
    int tid = threadIdx.x, lane = tid & 31, w = tid >> 5;
    int wn = w & 3, wm = w >> 2;            // 4x4 warps: wm -> 32-row strip, wn -> 64-col strip
    int m_block = blockIdx.x * 128;

    const __nv_bfloat16* AHs[2] = { selH(srcA1), selH(srcA2) };
    const __nv_bfloat16* ALs[2] = { selL(srcA1), selL(srcA2) };
    const __nv_bfloat16* BHs[2] = { g_Bh + (size_t)matB1*65536, g_Bh + (size_t)matB2*65536 };
    const __nv_bfloat16* BLs[2] = { g_Bl + (size_t)matB1*65536, g_Bl + (size_t)matB2*65536 };

    // ldmatrix per-lane offsets
    int sub = lane & 7, blk = lane >> 3;
    int rowoff = sub + ((blk & 1) << 3);
    uint32_t koffB = (uint32_t)((blk >> 1) << 4);   // 0 or 16 bytes
    uint32_t aoff[2][2], boff[4][2];
    #pragma unroll
    for (int mt = 0; mt < 2; ++mt)
        #pragma unroll
        for (int kh = 0; kh < 2; ++kh)
            aoff[mt][kh] = SW64((uint32_t)((wm*32 + mt*16 + rowoff)*64 + kh*32) + koffB);
    #pragma unroll
    for (int ng = 0; ng < 4; ++ng)
        #pragma unroll
        for (int kh = 0; kh < 2; ++kh)
            boff[ng][kh] = SW64((uint32_t)((wn*64 + ng*16 + rowoff)*64 + kh*32) + koffB);

    float c[2][8][4];
    #pragma unroll
    for (int mt = 0; mt < 2; ++mt)
        #pragma unroll
        for (int nt = 0; nt < 8; ++nt)
            #pragma unroll
            for (int i = 0; i < 4; ++i) c[mt][nt][i] = 0.f;

    int total = nsrc * 8;
    load_chunk(sb, AHs[0], ALs[0], BHs[0], BLs[0], m_block, 0, tid);
    CP_COMMIT();
    if (total > 1) {
        load_chunk(sb + BUF_BYTES, AHs[1>>3], ALs[1>>3], BHs[1>>3], BLs[1>>3], m_block, 1, tid);
        CP_COMMIT();
    }

    for (int ch = 0; ch < total; ++ch) {
        if (ch + 1 < total) CP_WAIT1(); else CP_WAIT0();
        __syncthreads();
        if (ch + 2 < total) {
            int nx = ch + 2, s = nx >> 3;
            load_chunk(sb + (nx % 3)*BUF_BYTES, AHs[s], ALs[s], BHs[s], BLs[s],
                       m_block, nx & 7, tid);
            CP_COMMIT();
        }
        uint32_t base = sb + (ch % 3)*BUF_BYTES;
        #pragma unroll
        for (int kh = 0; kh < 2; ++kh) {
            uint32_t ah[2][4], al[2][4];
            ldsm4(ah[0], base + aoff[0][kh]);
            ldsm4(ah[1], base + aoff[1][kh]);
            ldsm4(al[0], base + OFF_AL + aoff[0][kh]);
            ldsm4(al[1], base + OFF_AL + aoff[1][kh]);
            #pragma unroll
            for (int ng = 0; ng < 4; ++ng) {
                uint32_t bh[4], bl[4];
                ldsm4(bh, base + OFF_BH + boff[ng][kh]);
                ldsm4(bl, base + OFF_BL + boff[ng][kh]);
                #pragma unroll
                for (int mt = 0; mt < 2; ++mt) {
                    mma16816(c[mt][2*ng],   ah[mt], bh[0], bh[2]);
                    mma16816(c[mt][2*ng+1], ah[mt], bh[1], bh[3]);
                    mma16816(c[mt][2*ng],   al[mt], bh[0], bh[2]);
                    mma16816(c[mt][2*ng+1], al[mt], bh[1], bh[3]);
                    mma16816(c[mt][2*ng],   ah[mt], bl[0], bl[2]);
                    mma16816(c[mt][2*ng+1], ah[mt], bl[1], bl[3]);
                }
            }
        }
    }
    __syncthreads();

    // ======== fragment-direct epilogue ========
    float* sLN  = (float*)smraw;         // [128][4]
    float* sLN2 = sLN + 512;             // [128][4]
    int r4 = lane >> 2, kp2 = (lane & 3)*2;

    // bias add (all modes with bias)
    if (bias) {
        #pragma unroll
        for (int nt = 0; nt < 8; ++nt) {
            float2 bv = *(const float2*)(bias + wn*64 + nt*8 + kp2);
            #pragma unroll
            for (int mt = 0; mt < 2; ++mt) {
                c[mt][nt][0] += bv.x; c[mt][nt][1] += bv.y;
                c[mt][nt][2] += bv.x; c[mt][nt][3] += bv.y;
            }
        }
    }

    float muv[2][2], rsv[2][2];
    if (mode == MODE_LN) {
        #pragma unroll
        for (int mt = 0; mt < 2; ++mt)
            #pragma unroll
            for (int hf = 0; hf < 2; ++hf) {
                float s = 0.f, ss = 0.f;
                #pragma unroll
                for (int nt = 0; nt < 8; ++nt) {
                    float v0 = c[mt][nt][2*hf], v1 = c[mt][nt][2*hf+1];
                    s += v0 + v1; ss += v0*v0 + v1*v1;
                }
                s  += __shfl_xor_sync(0xffffffffu, s, 1);  s += __shfl_xor_sync(0xffffffffu, s, 2);
                ss += __shfl_xor_sync(0xffffffffu, ss, 1); ss += __shfl_xor_sync(0xffffffffu, ss, 2);
                if ((lane & 3) == 0) {
                    int rl = wm*32 + mt*16 + hf*8 + r4;
                    sLN[rl*4 + wn] = s; sLN2[rl*4 + wn] = ss;
                }
            }
        __syncthreads();
        #pragma unroll
        for (int mt = 0; mt < 2; ++mt)
            #pragma unroll
            for (int hf = 0; hf < 2; ++hf) {
                int rl = wm*32 + mt*16 + hf*8 + r4;
                float S  = sLN[rl*4] + sLN[rl*4+1] + sLN[rl*4+2] + sLN[rl*4+3];
                float SS = sLN2[rl*4] + sLN2[rl*4+1] + sLN2[rl*4+2] + sLN2[rl*4+3];
                float mu = S * (1.f/256.f);
                muv[mt][hf] = mu;
                rsv[mt][hf] = rsqrtf(SS * (1.f/256.f) - mu*mu + 1e-5f);
            }
    }

    // per-row coords (basis)
    float cx[2][2], cy[2][2], rr2[2][2];
    if (mode == MODE_BASIS) {
        #pragma unroll
        for (int mt = 0; mt < 2; ++mt)
            #pragma unroll
            for (int hf = 0; hf < 2; ++hf) {
                int pt = m_block + wm*32 + mt*16 + hf*8 + r4;
                float2 xy = *(const float2*)(coords + 2*pt);
                cx[mt][hf] = xy.x; cy[mt][hf] = xy.y; rr2[mt][hf] = xy.x*xy.x + xy.y*xy.y;
            }
    }

    __nv_bfloat16* oH = selH(dst);
    __nv_bfloat16* oL = selL(dst);
    #pragma unroll
    for (int nt = 0; nt < 8; ++nt) {
        int col = wn*64 + nt*8 + kp2;
        float lg0 = 0.f, lg1 = 0.f, lb0 = 0.f, lb1 = 0.f;
        float wx0=0,wy0=0,wx1=0,wy1=0,b0=0,b1=0,mx0=0,my0=0,mx1=0,my1=0,ga0=0,ga1=0,mu20=0,mu21=0;
        if (mode == MODE_LN) {
            float2 lg = *(const float2*)(lng + col);
            float2 lb = *(const float2*)(lnb + col);
            lg0 = lg.x; lg1 = lg.y; lb0 = lb.x; lb1 = lb.y;
        } else if (mode == MODE_BASIS) {
            int idx = L*256 + col;
            float4 wv = *(const float4*)(gW + 2*idx);
            float4 mv = *(const float4*)(gmu + 2*idx);
            float2 bv = *(const float2*)(gb + idx);
            float2 gv = *(const float2*)(gga + idx);
            wx0=wv.x; wy0=wv.y; wx1=wv.z; wy1=wv.w;
            mx0=mv.x; my0=mv.y; mx1=mv.z; my1=mv.w;
            b0=bv.x; b1=bv.y; ga0=gv.x; ga1=gv.y;
            mu20 = mx0*mx0 + my0*my0; mu21 = mx1*mx1 + my1*my1;
        }
        #pragma unroll
        for (int mt = 0; mt < 2; ++mt)
            #pragma unroll
            for (int hf = 0; hf < 2; ++hf) {
                int pt = m_block + wm*32 + mt*16 + hf*8 + r4;
                float v0 = c[mt][nt][2*hf], v1 = c[mt][nt][2*hf+1];
                if (mode == MODE_LN) {
                    v0 = (v0 - muv[mt][hf]) * rsv[mt][hf] * lg0 + lb0;
                    v1 = (v1 - muv[mt][hf]) * rsv[mt][hf] * lg1 + lb1;
                } else if (mode == MODE_BASIS) {
                    float x = cx[mt][hf], y = cy[mt][hf], r2 = rr2[mt][hf];
                    float D0 = r2 + mu20 - 2.f*(x*mx0 + y*my0);
                    float D1 = r2 + mu21 - 2.f*(x*mx1 + y*my1);
                    v0 *= sinf(wx0*x + wy0*y + b0) * __expf(-0.5f*D0*ga0);
                    v1 *= sinf(wx1*x + wy1*y + b1) * __expf(-0.5f*D1*ga1);
                }
                if (mode == MODE_Q) {
                    float2 qv = make_float2(v0*scale, v1*scale);
                    *(float2*)(g_Q + (size_t)pt*256 + col) = qv;
                } else {
                    __nv_bfloat16 h0 = __float2bfloat16_rn(v0);
                    __nv_bfloat16 h1 = __float2bfloat16_rn(v1);
                    __nv_bfloat16 l0 = __float2bfloat16_rn(v0 - __bfloat162float(h0));
                    __nv_bfloat16 l1 = __float2bfloat16_rn(v1 - __bfloat162float(h1));
                    uint32_t hp, lp;
                    { unsigned short a = *(unsigned short*)&h0, bsh = *(unsigned short*)&h1; hp = (uint32_t)a | ((uint32_t)bsh << 16); }
                    { unsigned short a = *(unsigned short*)&l0, bsh = *(unsigned short*)&l1; lp = (uint32_t)a | ((uint32_t)bsh << 16); }
                    *(uint32_t*)(oH + (size_t)pt*256 + col) = hp;
                    *(uint32_t*)(oL + (size_t)pt*256 + col) = lp;
                }
            }
    }
}

// ======== attention (scalar) ========
#define ATTN_SMF (5120 + P*512)
__global__ void __launch_bounds__(256, 2) attn_kernel() {
    extern __shared__ float smf[];
    float* sA = smf;
    float* sS = sA + 5120;
    int t = threadIdx.x, lane = t & 31, w = t >> 5;
    int bid = blockIdx.x, b = bid >> 10, n0 = (bid & 1023) * P;
    size_t base = (size_t)(b*NPTS + n0) * 256;
    #pragma unroll
    for (int p = 0; p < P; ++p) sA[t*PP + p] = g_Q[base + (size_t)p*256 + t];
    __syncthreads();
    #pragma unroll
    for (int rep = 0; rep < 2; ++rep) {
        int pair = t + rep*256, hh = pair >> 6, m = pair & 63;
        const float* Kp = &g_Kt[((b*8 + hh)*32)*M_KV + m];
        ull a2[8];
        #pragma unroll
        for (int j = 0; j < 8; ++j) a2[j] = 0ull;
        #pragma unroll 4
        for (int k = 0; k < 32; ++k) {
            float kv = Kp[k*M_KV];
            ull kk = pack2(kv, kv);
            const ulonglong2* col = (const ulonglong2*)(sA + (hh*32 + k)*PP);
            #pragma unroll
            for (int q = 0; q < 4; ++q) { ulonglong2 x = col[q]; fma2(a2[2*q], x.x, kk); fma2(a2[2*q+1], x.y, kk); }
        }
        #pragma unroll
        for (int j = 0; j < 8; ++j) {
            float lo, hi; unpack2(a2[j], lo, hi);
            sS[(2*j)*512 + pair] = lo; sS[(2*j+1)*512 + pair] = hi;
        }
    }
    __syncthreads();
    for (int rr = 0; rr < 16; ++rr) {
        int r = w + rr*8, p = r >> 3, hh = r & 7;
        float* bs = &sS[p*512 + hh*64];
        float v0 = bs[lane], v1 = bs[lane+32];
        float mx = fmaxf(v0, v1);
        #pragma unroll
        for (int o = 16; o; o >>= 1) mx = fmaxf(mx, __shfl_xor_sync(0xffffffffu, mx, o));
        float e0 = __expf(v0-mx), e1 = __expf(v1-mx), sum = e0 + e1;
        #pragma unroll
        for (int o = 16; o; o >>= 1) sum += __shfl_xor_sync(0xffffffffu, sum, o);
        float inv = 1.f/sum;
        bs[lane] = e0*inv; bs[lane+32] = e1*inv;
    }
    __syncthreads();
    {
        int hh = t >> 5;
        ull acc[P];
        #pragma unroll
        for (int p = 0; p < P; ++p) acc[p] = 0ull;
        const float* Vb = g_Vt + b*32*512;
        #pragma unroll 2
        for (int m = 0; m < M_KV; m += 2) {
            ull vv = *(const ull*)(Vb + ((m>>1)*256 + t)*2);
            #pragma unroll
            for (int p = 0; p < P; ++p) fma2(acc[p], *(const ull*)(&sS[p*512 + hh*64 + m]), vv);
        }
        #pragma unroll
        for (int p = 0; p < P; ++p) {
            float v = fold2(acc[p]);
            __nv_bfloat16 h = __float2bfloat16_rn(v);
            g_X0h[base + (size_t)p*256 + t] = h;
            g_X0l[base + (size_t)p*256 + t] = __float2bfloat16_rn(v - __bfloat162float(h));
        }
    }
}

// ======== fin + irfft ========
__global__ void __launch_bounds__(256, 2)
fin_kernel(const float* __restrict__ fin_W, const float* __restrict__ fin_b,
           float* __restrict__ out) {
    __shared__ float sA[256*PP];
    __shared__ float sF[P*36];
    __shared__ float sTab[32];
    int t = threadIdx.x;
    int bid = blockIdx.x, b = bid >> 10, n0 = (bid & 1023) * P;
    size_t base = (size_t)(b*NPTS + n0) * 256;
    if (t < 16) {
        float sv, cv;
        sincosf(0.39269908169872414f * (float)t, &sv, &cv);
        sTab[2*t] = cv; sTab[2*t+1] = sv;
    }
    #pragma unroll
    for (int p = 0; p < P; ++p)
        sA[t*PP + p] = __bfloat162float(g_X0h[base + (size_t)p*256 + t])
                     + __bfloat162float(g_X0l[base + (size_t)p*256 + t]);
    __syncthreads();
    {
        int g = t >> 2, j = t & 3;
        ull part2[8];
        #pragma unroll
        for (int q = 0; q < 8; ++q) part2[q] = 0ull;
        if (g < 36) {
            const float* Wo = &fin_W[g*256];
            #pragma unroll 4
            for (int k = 0; k < 64; ++k) {
                int h = (k << 2) + j;
                float wv = Wo[h];
                ull ww = pack2(wv, wv);
                const ulonglong2* col = (const ulonglong2*)(sA + h*PP);
                #pragma unroll
                for (int q = 0; q < 4; ++q) { ulonglong2 x = col[q]; fma2(part2[2*q], x.x, ww); fma2(part2[2*q+1], x.y, ww); }
            }
        }
        float part[P];
        #pragma unroll
        for (int q = 0; q < 8; ++q) unpack2(part2[q], part[2*q], part[2*q+1]);
        #pragma unroll
        for (int p = 0; p < P; ++p) {
            part[p] += __shfl_xor_sync(0xffffffffu, part[p], 1);
            part[p] += __shfl_xor_sync(0xffffffffu, part[p], 2);
        }
        if (g < 36 && j == 0) {
            float bb = fin_b[g];
            #pragma unroll
            for (int p = 0; p < P; ++p) sF[p*36 + g] = part[p] + bb;
        }
    }
    __syncthreads();
    {
        int inner = t & 31, p = inner >> 1, c = inner & 1;
        const float* Fp = &sF[p*36];
        #pragma unroll
        for (int it = 0; it < 2; ++it) {
            int tt = (t >> 5) + 8*it;
            float a = Fp[c*2];
            float f8 = Fp[8*4 + c*2];
            a += (tt & 1) ? -f8 : f8;
            #pragma unroll
            for (int fq = 1; fq < 8; ++fq) {
                float re = Fp[fq*4 + c*2], im = Fp[fq*4 + c*2 + 1];
                int k = (fq*tt) & 15;
                a += 2.f * (re*sTab[2*k] - im*sTab[2*k+1]);
            }
            out[(((b*16 + tt)*NPTS) + n0 + p)*2 + c] = 0.25f * a;
        }
    }
}

// ======== launch ========
extern "C" void kernel_launch(void* const* d_in, const int* in_sizes, int n_in,
                              void* d_out, int out_size) {
    const float* z_multi=(const float*)d_in[0];  const float* coords=(const float*)d_in[1];
    const float* gabor_W=(const float*)d_in[2];  const float* gabor_b=(const float*)d_in[3];
    const float* gabor_mu=(const float*)d_in[4]; const float* gabor_ga=(const float*)d_in[5];
    const float* net1_W=(const float*)d_in[6];   const float* net1_b=(const float*)d_in[7];
    const float* net2_W=(const float*)d_in[8];   const float* qp_W1=(const float*)d_in[9];
    const float* qp_b1=(const float*)d_in[10];   const float* qp_W2=(const float*)d_in[11];
    const float* qp_b2=(const float*)d_in[12];   const float* in_W=(const float*)d_in[13];
    const float* in_b=(const float*)d_in[14];    const float* out_W=(const float*)d_in[15];
    const float* out_b=(const float*)d_in[16];   const float* lnq_g=(const float*)d_in[17];
    const float* lnq_b=(const float*)d_in[18];   const float* lnkv_g=(const float*)d_in[19];
    const float* lnkv_b=(const float*)d_in[20];  const float* fin_W=(const float*)d_in[21];
    const float* fin_b=(const float*)d_in[22];
    float* out = (float*)d_out;

    cudaFuncSetAttribute(gemm_mma, cudaFuncAttributeMaxDynamicSharedMemorySize, GEMM_SMEM);
    cudaFuncSetAttribute(attn_kernel, cudaFuncAttributeMaxDynamicSharedMemorySize, ATTN_SMF*4);

    conv_w<<<dim3(256,14), 256>>>(qp_W2, in_W, out_W, net2_W, net1_W);
    kv_kernel<<<BATCH*M_KV/8, 256>>>(z_multi, lnkv_g, lnkv_b, in_b);
    gelu_kernel<<<TOTM/8, 256>>>(coords, qp_W1, qp_b1);

    int G = TOTM/128;
    const float qscale = 0.17677669529663687f;  // 1/sqrt(32)
    gemm_mma<<<G,512,GEMM_SMEM>>>(MODE_LN,0,1, 0,0, 0,0, 1, qp_b2,1.f, lnq_g,lnq_b, 0,0,0,0, 0);
    gemm_mma<<<G,512,GEMM_SMEM>>>(MODE_Q,0,1, 1,0, 1,0, 0, in_b,qscale, 0,0, 0,0,0,0, 0);
    attn_kernel<<<BATCH*(NPTS/P), 256, ATTN_SMF*4>>>();
    gemm_mma<<<G,512,GEMM_SMEM>>>(MODE_BIAS,0,1, 0,0, 2,0, 2, out_b,1.f, 0,0, 0,0,0,0, 0);
    gemm_mma<<<G,512,GEMM_SMEM>>>(MODE_BASIS,0,1, 2,0, 3,0, 0, (const float*)0,1.f, 0,0,
                                  gabor_W,gabor_b,gabor_mu,gabor_ga, coords);
    gemm_mma<<<G,512,GEMM_SMEM>>>(MODE_BASIS,1,2, 0,2, 8,4, 1, net1_b+0,1.f, 0,0,
                                  gabor_W,gabor_b,gabor_mu,gabor_ga, coords);
    gemm_mma<<<G,512,GEMM_SMEM>>>(MODE_BASIS,2,2, 1,2, 9,5, 0, net1_b+256,1.f, 0,0,
                                  gabor_W,gabor_b,gabor_mu,gabor_ga, coords);
    gemm_mma<<<G,512,GEMM_SMEM>>>(MODE_BASIS,3,2, 0,2, 10,6, 1, net1_b+512,1.f, 0,0,
                                  gabor_W,gabor_b,gabor_mu,gabor_ga, coords);
    gemm_mma<<<G,512,GEMM_SMEM>>>(MODE_BASIS,4,2, 1,2, 11,7, 0, net1_b+768,1.f, 0,0,
                                  gabor_W,gabor_b,gabor_mu,gabor_ga, coords);
    fin_kernel<<<BATCH*(NPTS/P), 256>>>(fin_W, fin_b, out);
}

// round 11
// speedup vs baseline: 2.7654x; 1.1900x over previous
#include <cuda_runtime.h>
#include <cuda_bf16.h>
#include <math.h>
#include <stdint.h>

#define BATCH 8
#define NPTS  16384
#define M_KV  64
#define TOTM  (BATCH*NPTS)
#define P     16
#define PP    20
typedef unsigned long long ull;

// ======== PTX helpers ========
__device__ __forceinline__ uint32_t smem_u32(const void* p) {
    uint32_t a;
    asm("{ .reg .u64 t; cvta.to.shared.u64 t, %1; cvt.u32.u64 %0, t; }" : "=r"(a) : "l"(p));
    return a;
}
#define CP16(dst, src) asm volatile("cp.async.cg.shared.global [%0], [%1], 16;" :: "r"(dst), "l"(src) : "memory")
#define CP_COMMIT()    asm volatile("cp.async.commit_group;" ::: "memory")
#define CP_WAIT1()     asm volatile("cp.async.wait_group 1;" ::: "memory")
#define CP_WAIT0()     asm volatile("cp.async.wait_group 0;" ::: "memory")
__device__ __forceinline__ void ldsm4(uint32_t* r, uint32_t addr) {
    asm volatile("ldmatrix.sync.aligned.m8n8.x4.shared.b16 {%0,%1,%2,%3}, [%4];"
        : "=r"(r[0]), "=r"(r[1]), "=r"(r[2]), "=r"(r[3]) : "r"(addr));
}
__device__ __forceinline__ void mma16816(float* c, const uint32_t* a, uint32_t b0, uint32_t b1) {
    asm volatile("mma.sync.aligned.m16n8k16.row.col.f32.bf16.bf16.f32 "
        "{%0,%1,%2,%3}, {%4,%5,%6,%7}, {%8,%9}, {%0,%1,%2,%3};"
        : "+f"(c[0]), "+f"(c[1]), "+f"(c[2]), "+f"(c[3])
        : "r"(a[0]), "r"(a[1]), "r"(a[2]), "r"(a[3]), "r"(b0), "r"(b1));
}
#define SW64(o) ((o) ^ (((o) >> 3) & 0x30))
__device__ __forceinline__ void fma2(ull& a, ull x, ull w) {
    asm("fma.rn.f32x2 %0, %1, %2, %0;" : "+l"(a) : "l"(x), "l"(w));
}
__device__ __forceinline__ float fold2(ull v) { float lo,hi; asm("mov.b64 {%0,%1}, %2;" : "=f"(lo),"=f"(hi) : "l"(v)); return lo+hi; }
__device__ __forceinline__ void unpack2(ull v, float& lo, float& hi) { asm("mov.b64 {%0,%1}, %2;" : "=f"(lo),"=f"(hi) : "l"(v)); }
__device__ __forceinline__ ull pack2(float lo, float hi) { ull r; asm("mov.b64 %0, {%1,%2};" : "=l"(r) : "f"(lo),"f"(hi)); return r; }
__device__ __forceinline__ uint32_t packbf(float v0, float v1, float& r0, float& r1) {
    __nv_bfloat16 h0 = __float2bfloat16_rn(v0);
    __nv_bfloat16 h1 = __float2bfloat16_rn(v1);
    r0 = v0 - __bfloat162float(h0);
    r1 = v1 - __bfloat162float(h1);
    unsigned short a = *(unsigned short*)&h0, b = *(unsigned short*)&h1;
    return (uint32_t)a | ((uint32_t)b << 16);
}

// ======== global scratch ========
#define SZ ((size_t)TOTM * 256)
__device__ __nv_bfloat16 g_X0h[SZ], g_X0l[SZ], g_X1h[SZ], g_X1l[SZ], g_Z2h[SZ], g_Z2l[SZ];
__device__ float g_Q[SZ];   // Q for attention; later reused for fp32 MFN output x
__device__ __nv_bfloat16 g_Bh[12*65536], g_Bl[12*65536];
__device__ float g_WkT[65536], g_WvT[65536];
__device__ float g_Kt[BATCH*8*32*M_KV];
__device__ float g_Vt[BATCH*32*256*2];
__device__ __forceinline__ __nv_bfloat16* selH(int s){ return s==0?g_X0h:(s==1?g_X1h:g_Z2h); }
__device__ __forceinline__ __nv_bfloat16* selL(int s){ return s==0?g_X0l:(s==1?g_X1l:g_Z2l); }

// ======== prep kernels ========
__global__ void conv_w(const float* __restrict__ qp_W2, const float* __restrict__ in_W,
                       const float* __restrict__ out_W, const float* __restrict__ net2_W,
                       const float* __restrict__ net1_W) {
    int n = blockIdx.x, mat = blockIdx.y, k = threadIdx.x;
    if (mat >= 12) {
        const float* src = in_W + (size_t)(mat == 12 ? 256 : 512) * 256;
        float* dst = (mat == 12) ? g_WkT : g_WvT;
        dst[k*256 + n] = src[n*256 + k];
        return;
    }
    const float* src;
    switch (mat) {
        case 0: src = qp_W2; break;
        case 1: src = in_W;  break;
        case 2: src = out_W; break;
        default: src = (mat < 8) ? net2_W + (mat-3)*65536 : net1_W + (mat-8)*65536;
    }
    float w = src[n*256 + k];
    __nv_bfloat16 h = __float2bfloat16_rn(w);
    g_Bh[mat*65536 + n*256 + k] = h;
    g_Bl[mat*65536 + n*256 + k] = __float2bfloat16_rn(w - __bfloat162float(h));
}

__global__ void kv_kernel(const float* __restrict__ z_multi,
                          const float* __restrict__ lnkv_g, const float* __restrict__ lnkv_b,
                          const float* __restrict__ in_b) {
    __shared__ float kvn[8][256];
    int t = threadIdx.x, lane = t & 31, w = t >> 5;
    int row0 = blockIdx.x * 8;
    {
        int row = row0 + w;
        float v[8];
        float s = 0.f, ss = 0.f;
        #pragma unroll
        for (int j = 0; j < 8; ++j) {
            v[j] = z_multi[(size_t)row*256 + lane*8 + j];
            s += v[j]; ss += v[j]*v[j];
        }
        #pragma unroll
        for (int o = 16; o; o >>= 1) {
            s  += __shfl_xor_sync(0xffffffffu, s,  o);
            ss += __shfl_xor_sync(0xffffffffu, ss, o);
        }
        float mu = s * (1.f/256.f);
        float rstd = rsqrtf(ss * (1.f/256.f) - mu*mu + 1e-5f);
        #pragma unroll
        for (int j = 0; j < 8; ++j) {
            int d = lane*8 + j;
            kvn[w][d] = (v[j] - mu) * rstd * lnkv_g[d] + lnkv_b[d];
        }
    }
    __syncthreads();
    float aK[8], aV[8];
    float bK = in_b[256+t], bV = in_b[512+t];
    #pragma unroll
    for (int i = 0; i < 8; ++i) { aK[i] = bK; aV[i] = bV; }
    #pragma unroll 4
    for (int d = 0; d < 256; ++d) {
        float wk = g_WkT[d*256 + t];
        float wv = g_WvT[d*256 + t];
        #pragma unroll
        for (int i = 0; i < 8; ++i) {
            float x = kvn[i][d];
            aK[i] += x * wk;
            aV[i] += x * wv;
        }
    }
    #pragma unroll
    for (int i = 0; i < 8; ++i) {
        int row = row0 + i, b = row >> 6, m = row & 63;
        g_Kt[((b*8 + (t>>5))*32 + (t&31))*M_KV + m] = aK[i];
        g_Vt[((b*32 + (m>>1))*256 + t)*2 + (m&1)] = aV[i];
    }
}

// ======== warp-MMA GEMM (templated mode) ========
#define OFF_AL 8192u
#define OFF_BH 16384u
#define OFF_BL 32768u
#define BUF_BYTES 49152u
#define GEMM_SMEM (3*49152)
#define MODE_LN 0      // fused gelu A-compute + LayerNorm epilogue
#define MODE_Q 1
#define MODE_BIAS 2
#define MODE_BASIS 3   // Gabor epilogue, bf16 h/l out
#define MODE_BASISQ 4  // Gabor epilogue, fp32 out to g_Q (final layer)

template<bool COMPUTE_A>
__device__ __forceinline__ void load_chunk(uint32_t base,
        const __nv_bfloat16* AH, const __nv_bfloat16* AL,
        const __nv_bfloat16* BH, const __nv_bfloat16* BL,
        int m0, int c, int tid,
        float cxp, float cyp,
        const float* __restrict__ qpW1, const float* __restrict__ qpb1) {
    int r = tid >> 2, seg = tid & 3;
    uint32_t sA = base + SW64((uint32_t)(r*64 + seg*16));
    if (COMPUTE_A) {
        // gelu(x0 @ qp_W1^T + b1) for hidden cols c*32 + seg*8 .. +7
        int h0 = c*32 + seg*8;
        #pragma unroll
        for (int j2 = 0; j2 < 4; ++j2) {
            int h = h0 + j2*2;
            float4 wv = *(const float4*)(qpW1 + 2*h);     // wx0,wy0,wx1,wy1
            float2 bv = *(const float2*)(qpb1 + h);
            float u0 = wv.x*cxp + wv.y*cyp + bv.x;
            float u1 = wv.z*cxp + wv.w*cyp + bv.y;
            float v0 = 0.5f*u0*(1.f + erff(u0*0.70710678118654752f));
            float v1 = 0.5f*u1*(1.f + erff(u1*0.70710678118654752f));
            float l0, l1;
            uint32_t hp = packbf(v0, v1, l0, l1);
            __nv_bfloat16 lb0 = __float2bfloat16_rn(l0);
            __nv_bfloat16 lb1 = __float2bfloat16_rn(l1);
            unsigned short a = *(unsigned short*)&lb0, b = *(unsigned short*)&lb1;
            uint32_t lp = (uint32_t)a | ((uint32_t)b << 16);
            *(uint32_t*)(uintptr_t)0;  // placeholder removed below
            asm volatile("st.shared.b32 [%0], %1;" :: "r"(sA + j2*4), "r"(hp) : "memory");
            asm volatile("st.shared.b32 [%0], %1;" :: "r"(sA + OFF_AL + j2*4), "r"(lp) : "memory");
        }
    } else {
        size_t aofs = (size_t)(m0 + r)*256 + c*32 + seg*8;
        CP16(sA, AH + aofs);
        CP16(sA + OFF_AL, AL + aofs);
    }
    #pragma unroll
    for (int it = 0; it < 2; ++it) {
        int row = r + it*128;
        size_t bofs = (size_t)row*256 + c*32 + seg*8;
        uint32_t sB = base + OFF_BH + SW64((uint32_t)(row*64 + seg*16));
        CP16(sB, BH + bofs);
        CP16(sB + 16384u, BL + bofs);
    }
}

template<int MODE>
__global__ void __launch_bounds__(512, 1)
gemm_mma(int L, int nsrc, int srcA1, int srcA2, int matB1, int matB2, int dst,
         const float* __restrict__ bias, float scale,
         const float* __restrict__ lng, const float* __restrict__ lnb,
         const float* __restrict__ gW, const float* __restrict__ gb,
         const float* __restrict__ gmu, const float* __restrict__ gga,
         const float* __restrict__ coords,
         const float* __restrict__ qpW1, const float* __restrict__ qpb1) {
    extern __shared__ char smraw[];
    uint32_t sb = smem_u32(smraw);
    int tid = threadIdx.x, lane = tid & 31, w = tid >> 5;
    int wn = w & 3, wm = w >> 2;
    int m_block = blockIdx.x * 128;

    const __nv_bfloat16* AHs[2] = { selH(srcA1), selH(srcA2) };
    const __nv_bfloat16* ALs[2] = { selL(srcA1), selL(srcA2) };
    const __nv_bfloat16* BHs[2] = { g_Bh + (size_t)matB1*65536, g_Bh + (size_t)matB2*65536 };
    const __nv_bfloat16* BLs[2] = { g_Bl + (size_t)matB1*65536, g_Bl + (size_t)matB2*65536 };

    // for gelu A-compute: this thread's point
    float cxp = 0.f, cyp = 0.f;
    if (MODE == MODE_LN) {
        float2 xy = *(const float2*)(coords + 2*(m_block + (tid >> 2)));
        cxp = xy.x; cyp = xy.y;
    }
    constexpr bool CA = (MODE == MODE_LN);

    int sub = lane & 7, blk = lane >> 3;
    int rowoff = sub + ((blk & 1) << 3);
    uint32_t koffB = (uint32_t)((blk >> 1) << 4);
    uint32_t aoff[2][2], boff[4][2];
    #pragma unroll
    for (int mt = 0; mt < 2; ++mt)
        #pragma unroll
        for (int kh = 0; kh < 2; ++kh)
            aoff[mt][kh] = SW64((uint32_t)((wm*32 + mt*16 + rowoff)*64 + kh*32) + koffB);
    #pragma unroll
    for (int ng = 0; ng < 4; ++ng)
        #pragma unroll
        for (int kh = 0; kh < 2; ++kh)
            boff[ng][kh] = SW64((uint32_t)((wn*64 + ng*16 + rowoff)*64 + kh*32) + koffB);

    float c[2][8][4];
    #pragma unroll
    for (int mt = 0; mt < 2; ++mt)
        #pragma unroll
        for (int nt = 0; nt < 8; ++nt)
            #pragma unroll
            for (int i = 0; i < 4; ++i) c[mt][nt][i] = 0.f;

    int total = nsrc * 8;
    load_chunk<CA>(sb, AHs[0], ALs[0], BHs[0], BLs[0], m_block, 0, tid, cxp, cyp, qpW1, qpb1);
    CP_COMMIT();
    if (total > 1) {
        load_chunk<CA>(sb + BUF_BYTES, AHs[0], ALs[0], BHs[0], BLs[0], m_block, 1, tid, cxp, cyp, qpW1, qpb1);
        CP_COMMIT();
    }

    for (int ch = 0; ch < total; ++ch) {
        if (ch + 1 < total) CP_WAIT1(); else CP_WAIT0();
        __syncthreads();
        if (ch + 2 < total) {
            int nx = ch + 2, s = nx >> 3;
            load_chunk<CA>(sb + (nx % 3)*BUF_BYTES, AHs[s], ALs[s], BHs[s], BLs[s],
                           m_block, nx & 7, tid, cxp, cyp, qpW1, qpb1);
            CP_COMMIT();
        }
        uint32_t base = sb + (ch % 3)*BUF_BYTES;
        #pragma unroll
        for (int kh = 0; kh < 2; ++kh) {
            uint32_t ah[2][4], al[2][4];
            ldsm4(ah[0], base + aoff[0][kh]);
            ldsm4(ah[1], base + aoff[1][kh]);
            ldsm4(al[0], base + OFF_AL + aoff[0][kh]);
            ldsm4(al[1], base + OFF_AL + aoff[1][kh]);
            #pragma unroll
            for (int ng = 0; ng < 4; ++ng) {
                uint32_t bh[4], bl[4];
                ldsm4(bh, base + OFF_BH + boff[ng][kh]);
                ldsm4(bl, base + OFF_BL + boff[ng][kh]);
                #pragma unroll
                for (int mt = 0; mt < 2; ++mt) {
                    mma16816(c[mt][2*ng],   ah[mt], bh[0], bh[2]);
                    mma16816(c[mt][2*ng+1], ah[mt], bh[1], bh[3]);
                    mma16816(c[mt][2*ng],   al[mt], bh[0], bh[2]);
                    mma16816(c[mt][2*ng+1], al[mt], bh[1], bh[3]);
                    mma16816(c[mt][2*ng],   ah[mt], bl[0], bl[2]);
                    mma16816(c[mt][2*ng+1], ah[mt], bl[1], bl[3]);
                }
            }
        }
    }
    __syncthreads();

    // ======== fragment-direct epilogue ========
    float* sLN  = (float*)smraw;
    float* sLN2 = sLN + 512;
    int r4 = lane >> 2, kp2 = (lane & 3)*2;

    if (bias) {
        #pragma unroll
        for (int nt = 0; nt < 8; ++nt) {
            float2 bv = *(const float2*)(bias + wn*64 + nt*8 + kp2);
            #pragma unroll
            for (int mt = 0; mt < 2; ++mt) {
                c[mt][nt][0] += bv.x; c[mt][nt][1] += bv.y;
                c[mt][nt][2] += bv.x; c[mt][nt][3] += bv.y;
            }
        }
    }

    float muv[2][2], rsv[2][2];
    if (MODE == MODE_LN) {
        #pragma unroll
        for (int mt = 0; mt < 2; ++mt)
            #pragma unroll
            for (int hf = 0; hf < 2; ++hf) {
                float s = 0.f, ss = 0.f;
                #pragma unroll
                for (int nt = 0; nt < 8; ++nt) {
                    float v0 = c[mt][nt][2*hf], v1 = c[mt][nt][2*hf+1];
                    s += v0 + v1; ss += v0*v0 + v1*v1;
                }
                s  += __shfl_xor_sync(0xffffffffu, s, 1);  s += __shfl_xor_sync(0xffffffffu, s, 2);
                ss += __shfl_xor_sync(0xffffffffu, ss, 1); ss += __shfl_xor_sync(0xffffffffu, ss, 2);
                if ((lane & 3) == 0) {
                    int rl = wm*32 + mt*16 + hf*8 + r4;
                    sLN[rl*4 + wn] = s; sLN2[rl*4 + wn] = ss;
                }
            }
        __syncthreads();
        #pragma unroll
        for (int mt = 0; mt < 2; ++mt)
            #pragma unroll
            for (int hf = 0; hf < 2; ++hf) {
                int rl = wm*32 + mt*16 + hf*8 + r4;
                float S  = sLN[rl*4] + sLN[rl*4+1] + sLN[rl*4+2] + sLN[rl*4+3];
                float SS = sLN2[rl*4] + sLN2[rl*4+1] + sLN2[rl*4+2] + sLN2[rl*4+3];
                float mu = S * (1.f/256.f);
                muv[mt][hf] = mu;
                rsv[mt][hf] = rsqrtf(SS * (1.f/256.f) - mu*mu + 1e-5f);
            }
    }

    float cx[2][2], cy[2][2], rr2[2][2];
    if (MODE == MODE_BASIS || MODE == MODE_BASISQ) {
        #pragma unroll
        for (int mt = 0; mt < 2; ++mt)
            #pragma unroll
            for (int hf = 0; hf < 2; ++hf) {
                int pt = m_block + wm*32 + mt*16 + hf*8 + r4;
                float2 xy = *(const float2*)(coords + 2*pt);
                cx[mt][hf] = xy.x; cy[mt][hf] = xy.y; rr2[mt][hf] = xy.x*xy.x + xy.y*xy.y;
            }
    }

    __nv_bfloat16* oH = selH(dst);
    __nv_bfloat16* oL = selL(dst);
    #pragma unroll
    for (int nt = 0; nt < 8; ++nt) {
        int col = wn*64 + nt*8 + kp2;
        float lg0 = 0.f, lg1 = 0.f, lb0 = 0.f, lb1 = 0.f;
        float wx0=0,wy0=0,wx1=0,wy1=0,b0=0,b1=0,mx0=0,my0=0,mx1=0,my1=0,ga0=0,ga1=0,mu20=0,mu21=0;
        if (MODE == MODE_LN) {
            float2 lg = *(const float2*)(lng + col);
            float2 lb = *(const float2*)(lnb + col);
            lg0 = lg.x; lg1 = lg.y; lb0 = lb.x; lb1 = lb.y;
        } else if (MODE == MODE_BASIS || MODE == MODE_BASISQ) {
            int idx = L*256 + col;
            float4 wv = *(const float4*)(gW + 2*idx);
            float4 mv = *(const float4*)(gmu + 2*idx);
            float2 bv = *(const float2*)(gb + idx);
            float2 gv = *(const float2*)(gga + idx);
            wx0=wv.x; wy0=wv.y; wx1=wv.z; wy1=wv.w;
            mx0=mv.x; my0=mv.y; mx1=mv.z; my1=mv.w;
            b0=bv.x; b1=bv.y; ga0=gv.x; ga1=gv.y;
            mu20 = mx0*mx0 + my0*my0; mu21 = mx1*mx1 + my1*my1;
        }
        #pragma unroll
        for (int mt = 0; mt < 2; ++mt)
            #pragma unroll
            for (int hf = 0; hf < 2; ++hf) {
                int pt = m_block + wm*32 + mt*16 + hf*8 + r4;
                float v0 = c[mt][nt][2*hf], v1 = c[mt][nt][2*hf+1];
                if (MODE == MODE_LN) {
                    v0 = (v0 - muv[mt][hf]) * rsv[mt][hf] * lg0 + lb0;
                    v1 = (v1 - muv[mt][hf]) * rsv[mt][hf] * lg1 + lb1;
                } else if (MODE == MODE_BASIS || MODE == MODE_BASISQ) {
                    float x = cx[mt][hf], y = cy[mt][hf], r2 = rr2[mt][hf];
                    float D0 = r2 + mu20 - 2.f*(x*mx0 + y*my0);
                    float D1 = r2 + mu21 - 2.f*(x*mx1 + y*my1);
                    v0 *= sinf(wx0*x + wy0*y + b0) * __expf(-0.5f*D0*ga0);
                    v1 *= sinf(wx1*x + wy1*y + b1) * __expf(-0.5f*D1*ga1);
                }
                if (MODE == MODE_Q) {
                    *(float2*)(g_Q + (size_t)pt*256 + col) = make_float2(v0*scale, v1*scale);
                } else if (MODE == MODE_BASISQ) {
                    *(float2*)(g_Q + (size_t)pt*256 + col) = make_float2(v0, v1);
                } else {
                    float l0, l1;
                    uint32_t hp = packbf(v0, v1, l0, l1);
                    __nv_bfloat16 lo0 = __float2bfloat16_rn(l0);
                    __nv_bfloat16 lo1 = __float2bfloat16_rn(l1);
                    unsigned short a = *(unsigned short*)&lo0, bsh = *(unsigned short*)&lo1;
                    uint32_t lp = (uint32_t)a | ((uint32_t)bsh << 16);
                    *(uint32_t*)(oH + (size_t)pt*256 + col) = hp;
                    *(uint32_t*)(oL + (size_t)pt*256 + col) = lp;
                }
            }
    }
}

// ======== attention (scalar) ========
#define ATTN_SMF (5120 + P*512)
__global__ void __launch_bounds__(256, 2) attn_kernel() {
    extern __shared__ float smf[];
    float* sA = smf;
    float* sS = sA + 5120;
    int t = threadIdx.x, lane = t & 31, w = t >> 5;
    int bid = blockIdx.x, b = bid >> 10, n0 = (bid & 1023) * P;
    size_t base = (size_t)(b*NPTS + n0) * 256;
    #pragma unroll
    for (int p = 0; p < P; ++p) sA[t*PP + p] = g_Q[base + (size_t)p*256 + t];
    __syncthreads();
    #pragma unroll
    for (int rep = 0; rep < 2; ++rep) {
        int pair = t + rep*256, hh = pair >> 6, m = pair & 63;
        const float* Kp = &g_Kt[((b*8 + hh)*32)*M_KV + m];
        ull a2[8];
        #pragma unroll
        for (int j = 0; j < 8; ++j) a2[j] = 0ull;
        #pragma unroll 4
        for (int k = 0; k < 32; ++k) {
            float kv = Kp[k*M_KV];
            ull kk = pack2(kv, kv);
            const ulonglong2* col = (const ulonglong2*)(sA + (hh*32 + k)*PP);
            #pragma unroll
            for (int q = 0; q < 4; ++q) { ulonglong2 x = col[q]; fma2(a2[2*q], x.x, kk); fma2(a2[2*q+1], x.y, kk); }
        }
        #pragma unroll
        for (int j = 0; j < 8; ++j) {
            float lo, hi; unpack2(a2[j], lo, hi);
            sS[(2*j)*512 + pair] = lo; sS[(2*j+1)*512 + pair] = hi;
        }
    }
    __syncthreads();
    for (int rr = 0; rr < 16; ++rr) {
        int r = w + rr*8, p = r >> 3, hh = r & 7;
        float* bs = &sS[p*512 + hh*64];
        float v0 = bs[lane], v1 = bs[lane+32];
        float mx = fmaxf(v0, v1);
        #pragma unroll
        for (int o = 16; o; o >>= 1) mx = fmaxf(mx, __shfl_xor_sync(0xffffffffu, mx, o));
        float e0 = __expf(v0-mx), e1 = __expf(v1-mx), sum = e0 + e1;
        #pragma unroll
        for (int o = 16; o; o >>= 1) sum += __shfl_xor_sync(0xffffffffu, sum, o);
        float inv = 1.f/sum;
        bs[lane] = e0*inv; bs[lane+32] = e1*inv;
    }
    __syncthreads();
    {
        int hh = t >> 5;
        ull acc[P];
        #pragma unroll
        for (int p = 0; p < P; ++p) acc[p] = 0ull;
        const float* Vb = g_Vt + b*32*512;
        #pragma unroll 2
        for (int m = 0; m < M_KV; m += 2) {
            ull vv = *(const ull*)(Vb + ((m>>1)*256 + t)*2);
            #pragma unroll
            for (int p = 0; p < P; ++p) fma2(acc[p], *(const ull*)(&sS[p*512 + hh*64 + m]), vv);
        }
        #pragma unroll
        for (int p = 0; p < P; ++p) {
            float v = fold2(acc[p]);
            __nv_bfloat16 h = __float2bfloat16_rn(v);
            g_X0h[base + (size_t)p*256 + t] = h;
            g_X0l[base + (size_t)p*256 + t] = __float2bfloat16_rn(v - __bfloat162float(h));
        }
    }
}

// ======== fin + irfft (reads fp32 x from g_Q) ========
__global__ void __launch_bounds__(256, 2)
fin_kernel(const float* __restrict__ fin_W, const float* __restrict__ fin_b,
           float* __restrict__ out) {
    __shared__ float sA[256*PP];
    __shared__ float sF[P*36];
    __shared__ float sTab[32];
    int t = threadIdx.x;
    int bid = blockIdx.x, b = bid >> 10, n0 = (bid & 1023) * P;
    size_t base = (size_t)(b*NPTS + n0) * 256;
    if (t < 16) {
        float sv, cv;
        sincosf(0.39269908169872414f * (float)t, &sv, &cv);
        sTab[2*t] = cv; sTab[2*t+1] = sv;
    }
    #pragma unroll
    for (int p = 0; p < P; ++p)
        sA[t*PP + p] = g_Q[base + (size_t)p*256 + t];
    __syncthreads();
    {
        int g = t >> 2, j = t & 3;
        ull part2[8];
        #pragma unroll
        for (int q = 0; q < 8; ++q) part2[q] = 0ull;
        if (g < 36) {
            const float* Wo = &fin_W[g*256];
            #pragma unroll 4
            for (int k = 0; k < 64; ++k) {
                int h = (k << 2) + j;
                float wv = Wo[h];
                ull ww = pack2(wv, wv);
                const ulonglong2* col = (const ulonglong2*)(sA + h*PP);
                #pragma unroll
                for (int q = 0; q < 4; ++q) { ulonglong2 x = col[q]; fma2(part2[2*q], x.x, ww); fma2(part2[2*q+1], x.y, ww); }
            }
        }
        float part[P];
        #pragma unroll
        for (int q = 0; q < 8; ++q) unpack2(part2[q], part[2*q], part[2*q+1]);
        #pragma unroll
        for (int p = 0; p < P; ++p) {
            part[p] += __shfl_xor_sync(0xffffffffu, part[p], 1);
            part[p] += __shfl_xor_sync(0xffffffffu, part[p], 2);
        }
        if (g < 36 && j == 0) {
            float bb = fin_b[g];
            #pragma unroll
            for (int p = 0; p < P; ++p) sF[p*36 + g] = part[p] + bb;
        }
    }
    __syncthreads();
    {
        int inner = t & 31, p = inner >> 1, c = inner & 1;
        const float* Fp = &sF[p*36];
        #pragma unroll
        for (int it = 0; it < 2; ++it) {
            int tt = (t >> 5) + 8*it;
            float a = Fp[c*2];
            float f8 = Fp[8*4 + c*2];
            a += (tt & 1) ? -f8 : f8;
            #pragma unroll
            for (int fq = 1; fq < 8; ++fq) {
                float re = Fp[fq*4 + c*2], im = Fp[fq*4 + c*2 + 1];
                int k = (fq*tt) & 15;
                a += 2.f * (re*sTab[2*k] - im*sTab[2*k+1]);
            }
            out[(((b*16 + tt)*NPTS) + n0 + p)*2 + c] = 0.25f * a;
        }
    }
}

// ======== launch ========
extern "C" void kernel_launch(void* const* d_in, const int* in_sizes, int n_in,
                              void* d_out, int out_size) {
    const float* z_multi=(const float*)d_in[0];  const float* coords=(const float*)d_in[1];
    const float* gabor_W=(const float*)d_in[2];  const float* gabor_b=(const float*)d_in[3];
    const float* gabor_mu=(const float*)d_in[4]; const float* gabor_ga=(const float*)d_in[5];
    const float* net1_W=(const float*)d_in[6];   const float* net1_b=(const float*)d_in[7];
    const float* net2_W=(const float*)d_in[8];   const float* qp_W1=(const float*)d_in[9];
    const float* qp_b1=(const float*)d_in[10];   const float* qp_W2=(const float*)d_in[11];
    const float* qp_b2=(const float*)d_in[12];   const float* in_W=(const float*)d_in[13];
    const float* in_b=(const float*)d_in[14];    const float* out_W=(const float*)d_in[15];
    const float* out_b=(const float*)d_in[16];   const float* lnq_g=(const float*)d_in[17];
    const float* lnq_b=(const float*)d_in[18];   const float* lnkv_g=(const float*)d_in[19];
    const float* lnkv_b=(const float*)d_in[20];  const float* fin_W=(const float*)d_in[21];
    const float* fin_b=(const float*)d_in[22];
    float* out = (float*)d_out;

    cudaFuncSetAttribute(gemm_mma<MODE_LN>,     cudaFuncAttributeMaxDynamicSharedMemorySize, GEMM_SMEM);
    cudaFuncSetAttribute(gemm_mma<MODE_Q>,      cudaFuncAttributeMaxDynamicSharedMemorySize, GEMM_SMEM);
    cudaFuncSetAttribute(gemm_mma<MODE_BIAS>,   cudaFuncAttributeMaxDynamicSharedMemorySize, GEMM_SMEM);
    cudaFuncSetAttribute(gemm_mma<MODE_BASIS>,  cudaFuncAttributeMaxDynamicSharedMemorySize, GEMM_SMEM);
    cudaFuncSetAttribute(gemm_mma<MODE_BASISQ>, cudaFuncAttributeMaxDynamicSharedMemorySize, GEMM_SMEM);
    cudaFuncSetAttribute(attn_kernel, cudaFuncAttributeMaxDynamicSharedMemorySize, ATTN_SMF*4);

    conv_w<<<dim3(256,14), 256>>>(qp_W2, in_W, out_W, net2_W, net1_W);
    kv_kernel<<<BATCH*M_KV/8, 256>>>(z_multi, lnkv_g, lnkv_b, in_b);

    int G = TOTM/128;
    const float qscale = 0.17677669529663687f;  // 1/sqrt(32)
    // q = LN(gelu(x0@qpW1+b1) @ qpW2^T + b2) -> X1   (gelu fused into A-loader)
    gemm_mma<MODE_LN><<<G,512,GEMM_SMEM>>>(0,1, 0,0, 0,0, 1, qp_b2,1.f, lnq_g,lnq_b,
                                           0,0,0,0, coords, qp_W1, qp_b1);
    gemm_mma<MODE_Q><<<G,512,GEMM_SMEM>>>(0,1, 1,0, 1,0, 0, in_b,qscale, 0,0, 0,0,0,0, coords, 0,0);
    attn_kernel<<<BATCH*(NPTS/P), 256, ATTN_SMF*4>>>();
    gemm_mma<MODE_BIAS><<<G,512,GEMM_SMEM>>>(0,1, 0,0, 2,0, 2, out_b,1.f, 0,0, 0,0,0,0, coords, 0,0);
    gemm_mma<MODE_BASIS><<<G,512,GEMM_SMEM>>>(0,1, 2,0, 3,0, 0, (const float*)0,1.f, 0,0,
                                              gabor_W,gabor_b,gabor_mu,gabor_ga, coords, 0,0);
    gemm_mma<MODE_BASIS><<<G,512,GEMM_SMEM>>>(1,2, 0,2, 8,4, 1, net1_b+0,1.f, 0,0,
                                              gabor_W,gabor_b,gabor_mu,gabor_ga, coords, 0,0);
    gemm_mma<MODE_BASIS><<<G,512,GEMM_SMEM>>>(2,2, 1,2, 9,5, 0, net1_b+256,1.f, 0,0,
                                              gabor_W,gabor_b,gabor_mu,gabor_ga, coords, 0,0);
    gemm_mma<MODE_BASIS><<<G,512,GEMM_SMEM>>>(3,2, 0,2, 10,6, 1, net1_b+512,1.f, 0,0,
                                              gabor_W,gabor_b,gabor_mu,gabor_ga, coords, 0,0);
    gemm_mma<MODE_BASISQ><<<G,512,GEMM_SMEM>>>(4,2, 1,2, 11,7, 0, net1_b+768,1.f, 0,0,
                                               gabor_W,gabor_b,gabor_mu,gabor_ga, coords, 0,0);
    fin_kernel<<<BATCH*(NPTS/P), 256>>>(fin_W, fin_b, out);
}